// round 12
// baseline (speedup 1.0000x reference)
#include <cuda_runtime.h>
#include <cuda_bf16.h>

#define NIMG 8
#define CIN  256
#define HW   16384      // 128*128
#define C8   32

// ---------------------------------------------------------------------------
// Scratch
// ---------------------------------------------------------------------------
__device__ float    g_y1 [NIMG * CIN * HW];
__device__ float    g_fd [NIMG * CIN * HW];   // stage-1 fd / stage-2 zhat (bf16 view)
__device__ float    g_fbc[NIMG * 64  * HW];
__device__ unsigned g_wbf[CIN * 128];         // Wd2 as bf16 pairs [o][k/2]

// ---------------------------------------------------------------------------
// Helpers
// ---------------------------------------------------------------------------
__device__ __forceinline__ unsigned f2tf(float f) {
    unsigned u; asm("cvt.rna.tf32.f32 %0, %1;" : "=r"(u) : "f"(f)); return u;
}
__device__ __forceinline__ void mma_tf32(float* c, const unsigned* a, unsigned b0, unsigned b1) {
    asm volatile("mma.sync.aligned.m16n8k8.row.col.f32.tf32.tf32.f32 "
                 "{%0,%1,%2,%3}, {%4,%5,%6,%7}, {%8,%9}, {%0,%1,%2,%3};"
                 : "+f"(c[0]), "+f"(c[1]), "+f"(c[2]), "+f"(c[3])
                 : "r"(a[0]), "r"(a[1]), "r"(a[2]), "r"(a[3]), "r"(b0), "r"(b1));
}
__device__ __forceinline__ void mma_bf16(float* c, const unsigned* a, unsigned b0, unsigned b1) {
    asm volatile("mma.sync.aligned.m16n8k16.row.col.f32.bf16.bf16.f32 "
                 "{%0,%1,%2,%3}, {%4,%5,%6,%7}, {%8,%9}, {%0,%1,%2,%3};"
                 : "+f"(c[0]), "+f"(c[1]), "+f"(c[2]), "+f"(c[3])
                 : "r"(a[0]), "r"(a[1]), "r"(a[2]), "r"(a[3]), "r"(b0), "r"(b1));
}
__device__ __forceinline__ unsigned pkbf(float lo, float hi) {
    __nv_bfloat162 h = __floats2bfloat162_rn(lo, hi);
    return *(unsigned*)&h;
}
__device__ __forceinline__ void cp16(unsigned dst, const void* src) {
    asm volatile("cp.async.cg.shared.global [%0], [%1], 16;" :: "r"(dst), "l"(src));
}
__device__ __forceinline__ void cp_commit() { asm volatile("cp.async.commit_group;"); }
__device__ __forceinline__ void cp_wait0()  { asm volatile("cp.async.wait_group 0;"); }

// ===========================================================================
// conv_fbc_tc: fbc = [Wb;Wc].in + [bb;bc]   (M=64, tf32)
// BOTH operands via cp.async (raw fp32; tf32 mma truncates). Double-buffered.
// grid z==8 blocks (stage-2 only) pack Wfe -> g_wbf (bf16 pairs).
// Dynamic SMEM: Ws[2][64][36] | Xs[2][32][136]  = 53248 B
// ===========================================================================
#define FBC_SMEM ((2 * 64 * 36 + 2 * 32 * 136) * 4)

__global__ void __launch_bounds__(256, 3) conv_fbc_tc(
    const float* __restrict__ Wb, const float* __restrict__ bb,
    const float* __restrict__ Wc, const float* __restrict__ bc,
    const float* __restrict__ inA, const float* __restrict__ inB,
    const float* __restrict__ sel, const float* __restrict__ guard,
    const float* __restrict__ Wfe,
    float* __restrict__ out)
{
    if (guard[0] == 0.0f) return;

    if (blockIdx.z == 8) {                 // folded wcvt: pack Wfe to bf16 pairs
        int idx = blockIdx.x * 256 + threadIdx.x;   // 128 blocks x 256 = 32768
        int o = idx >> 7, kp = idx & 127;
        g_wbf[idx] = pkbf(Wfe[o * 256 + kp * 2], Wfe[o * 256 + kp * 2 + 1]);
        return;
    }

    const float* in = (sel[0] == 0.0f) ? inA : inB;
    const int b = blockIdx.z, p0 = blockIdx.x * 128;

    extern __shared__ float smf[];
    float* Wbuf = smf;                 // [2][64][36]
    float* Xbuf = smf + 2 * 64 * 36;   // [2][32][136]
    const unsigned wba = (unsigned)__cvta_generic_to_shared(Wbuf);
    const unsigned xba = (unsigned)__cvta_generic_to_shared(Xbuf);

    const int t = threadIdx.x, lane = t & 31, w = t >> 5;
    const int wm = w >> 2, wn = w & 3;
    const int g4 = lane >> 2, tg = lane & 3;

    float acc[2][4][4] = {};
    const float* inb = in + (size_t)b * CIN * HW + p0;

    auto issue = [&](int k0, int buf) {
        unsigned wd = wba + (unsigned)(buf * 64 * 36) * 4u;
        #pragma unroll
        for (int i = 0; i < 2; i++) {      // W chunk: 64 x 32 fp32
            int fi = i * 256 + t, o = fi >> 3, k4 = (fi & 7) * 4;
            const float* src = (o < 32) ? &Wb[o * 256 + k0 + k4]
                                        : &Wc[(o - 32) * 256 + k0 + k4];
            cp16(wd + (unsigned)(o * 36 + k4) * 4u, src);
        }
        unsigned xd = xba + (unsigned)(buf * 32 * 136) * 4u;
        #pragma unroll
        for (int i = 0; i < 4; i++) {      // X chunk: 32 x 128 fp32
            int fi = i * 256 + t, k = fi >> 5, seg = fi & 31;
            cp16(xd + (unsigned)(k * 136 + seg * 4) * 4u,
                 inb + (size_t)(k0 + k) * HW + seg * 4);
        }
        cp_commit();
    };

    issue(0, 0);
    cp_wait0(); __syncthreads();

    for (int c = 0; c < 8; c++) {
        if (c < 7) issue((c + 1) * 32, (c + 1) & 1);
        const float* Wd = Wbuf + (c & 1) * 64 * 36;
        const float* Xd = Xbuf + (c & 1) * 32 * 136;
        #pragma unroll
        for (int ks = 0; ks < 4; ks++) {
            unsigned a[2][4];
            int col = ks * 8 + tg;
            #pragma unroll
            for (int mt = 0; mt < 2; mt++) {
                int r = wm * 32 + mt * 16 + g4;
                a[mt][0] = __float_as_uint(Wd[r * 36 + col]);
                a[mt][1] = __float_as_uint(Wd[(r + 8) * 36 + col]);
                a[mt][2] = __float_as_uint(Wd[r * 36 + col + 4]);
                a[mt][3] = __float_as_uint(Wd[(r + 8) * 36 + col + 4]);
            }
            #pragma unroll
            for (int nt = 0; nt < 4; nt++) {
                int p = wn * 32 + nt * 8 + g4;
                unsigned b0 = __float_as_uint(Xd[(ks * 8 + tg) * 136 + p]);
                unsigned b1 = __float_as_uint(Xd[(ks * 8 + 4 + tg) * 136 + p]);
                mma_tf32(acc[0][nt], a[0], b0, b1);
                mma_tf32(acc[1][nt], a[1], b0, b1);
            }
        }
        if (c < 7) { cp_wait0(); __syncthreads(); }
    }

    #pragma unroll
    for (int mt = 0; mt < 2; mt++) {
        int o0 = wm * 32 + mt * 16 + g4, o1 = o0 + 8;
        float bs0 = (o0 < 32) ? bb[o0] : bc[o0 - 32];
        float bs1 = (o1 < 32) ? bb[o1] : bc[o1 - 32];
        #pragma unroll
        for (int nt = 0; nt < 4; nt++) {
            int p = p0 + wn * 32 + nt * 8 + tg * 2;
            *(float2*)&out[((size_t)b * 64 + o0) * HW + p] =
                make_float2(acc[mt][nt][0] + bs0, acc[mt][nt][1] + bs0);
            *(float2*)&out[((size_t)b * 64 + o1) * HW + p] =
                make_float2(acc[mt][nt][2] + bs1, acc[mt][nt][3] + bs1);
        }
    }
}

// ===========================================================================
// attn_zhat (occ 3): logits(fp32)+softmax, zhat = A.y^T bf16;
// zhat written bf16 to [n][pix][256c].
// ===========================================================================
#define ZA_YS  0
#define ZA_FB  (256 * 36)
#define ZA_AS  (ZA_FB + 64 * 68)
#define ZA_TOT (ZA_AS + 64 * 36)          // 15872 words = 63488 B

__global__ void __launch_bounds__(256, 3) attn_zhat(
    const float* __restrict__ x, const float* __restrict__ y1,
    const float* __restrict__ fbc,
    const float* __restrict__ alpha1_p, const float* __restrict__ alpha2_p,
    __nv_bfloat16* __restrict__ zout)
{
    if (alpha2_p[0] == 0.0f) return;
    const float* y = (alpha1_p[0] == 0.0f) ? x : y1;

    extern __shared__ unsigned smu[];
    unsigned* ysp = smu + ZA_YS;           // bf16 pairs along pixel m, stride 36
    float*    fb  = (float*)(smu + ZA_FB); // fp32, stride 68
    unsigned* Asp = smu + ZA_AS;           // bf16 pairs along m, stride 36
    unsigned* zh  = smu + ZA_YS;           // alias, stride 132

    const int beta = blockIdx.x;
    const int n  = beta >> 8;
    const int qh = (beta >> 4) & 15, qw = beta & 15;
    const int base = (qh * 8) * 128 + qw * 8;
    const int t = threadIdx.x, lane = t & 31, w = t >> 5;
    const int g4 = lane >> 2, tg = lane & 3;

    {
        const float* fbb = fbc + (size_t)n * 64 * HW + base;
        #pragma unroll
        for (int i = 0; i < 4; i++) {
            int fi = i * 256 + t;
            int r = fi >> 4, jr = (fi >> 1) & 7, jc = (fi & 1) * 4;
            *(float4*)&fb[r * 68 + jr * 8 + jc] = *(const float4*)&fbb[(size_t)r * HW + jr * 128 + jc];
        }
        const float* yb = y + (size_t)n * CIN * HW + base;
        #pragma unroll
        for (int i = 0; i < 16; i++) {
            int fi = i * 256 + t;
            int c = fi >> 4, jr = (fi >> 1) & 7, jc = (fi & 1) * 4;
            float4 v = *(const float4*)&yb[(size_t)c * HW + jr * 128 + jc];
            int j0 = jr * 4 + (jc >> 1);
            uint2 pk = make_uint2(pkbf(v.x, v.y), pkbf(v.z, v.w));
            *(uint2*)&ysp[c * 36 + j0] = pk;
        }
    }
    __syncthreads();

    {   // logits + softmax (fp32)
        const int l = t >> 2, mq = t & 3;
        float fbl[32];
        #pragma unroll
        for (int k = 0; k < 32; k++) fbl[k] = fb[k * 68 + l];
        float s[16];
        #pragma unroll
        for (int mm = 0; mm < 16; mm++) {
            int m = mq * 16 + mm;
            float v = 0.f;
            #pragma unroll
            for (int k = 0; k < 32; k++) v += fbl[k] * fb[(32 + k) * 68 + m];
            s[mm] = v;
        }
        float mx = -1e30f;
        #pragma unroll
        for (int i = 0; i < 16; i++) mx = fmaxf(mx, s[i]);
        mx = fmaxf(mx, __shfl_xor_sync(0xffffffff, mx, 1));
        mx = fmaxf(mx, __shfl_xor_sync(0xffffffff, mx, 2));
        float sum = 0.f;
        #pragma unroll
        for (int i = 0; i < 16; i++) { s[i] = __expf(s[i] - mx); sum += s[i]; }
        sum += __shfl_xor_sync(0xffffffff, sum, 1);
        sum += __shfl_xor_sync(0xffffffff, sum, 2);
        float inv = 1.0f / sum;
        #pragma unroll
        for (int q = 0; q < 8; q++)
            Asp[l * 36 + mq * 8 + q] = pkbf(s[2 * q] * inv, s[2 * q + 1] * inv);
    }
    __syncthreads();

    {   // zhat = A . y^T  (M64 l, N256 c, K64 m), bf16
        const int wm = w >> 2, wc = w & 3;
        const int m0 = wm * 32, c0w = wc * 64;
        float acc[2][8][4];
        #pragma unroll
        for (int i = 0; i < 2; i++)
            #pragma unroll
            for (int j = 0; j < 8; j++)
                #pragma unroll
                for (int q = 0; q < 4; q++) acc[i][j][q] = 0.f;
        #pragma unroll
        for (int ks = 0; ks < 4; ks++) {
            unsigned a[2][4];
            int col = ks * 8 + tg;
            #pragma unroll
            for (int mt = 0; mt < 2; mt++) {
                int r = m0 + mt * 16 + g4;
                a[mt][0] = Asp[r * 36 + col];
                a[mt][1] = Asp[(r + 8) * 36 + col];
                a[mt][2] = Asp[r * 36 + col + 4];
                a[mt][3] = Asp[(r + 8) * 36 + col + 4];
            }
            #pragma unroll
            for (int nt = 0; nt < 8; nt++) {
                int c = c0w + nt * 8 + g4;
                unsigned b0 = ysp[c * 36 + col];
                unsigned b1 = ysp[c * 36 + col + 4];
                mma_bf16(acc[0][nt], a[0], b0, b1);
                mma_bf16(acc[1][nt], a[1], b0, b1);
            }
        }
        __syncthreads();                       // ysp reads done -> zh alias safe
        #pragma unroll
        for (int mt = 0; mt < 2; mt++) {
            int l0 = m0 + mt * 16 + g4;
            #pragma unroll
            for (int nt = 0; nt < 8; nt++) {
                int cp = wc * 32 + nt * 4 + tg;
                zh[l0 * 132 + cp]       = pkbf(acc[mt][nt][0], acc[mt][nt][1]);
                zh[(l0 + 8) * 132 + cp] = pkbf(acc[mt][nt][2], acc[mt][nt][3]);
            }
        }
    }
    __syncthreads();

    {   // coalesced global write: [pix][c] bf16
        unsigned* zb = (unsigned*)zout + (size_t)n * HW * 128;
        #pragma unroll
        for (int i = 0; i < 32; i++) {
            int fi = i * 256 + t;
            int l = fi >> 7, cq = fi & 127;
            int pix = base + (l >> 3) * 128 + (l & 7);
            zb[(size_t)pix * 128 + cq] = zh[l * 132 + cq];
        }
    }
}

// ===========================================================================
// conv_fe v3: out = alpha*(Wd.zhat + bd) + y, bf16 mma, occ 3.
// Tiles: M=128 (mi), N=64 pixels (pi). grid (512, 1, NIMG).
// Dynamic SMEM: Wsp[2][128][20] | Xs[64][132]  = 54272 B
// ===========================================================================
#define FE_SMEM ((2 * 128 * 20 + 64 * 132) * 4)

__global__ void __launch_bounds__(256, 3) conv_fe_bf(
    const float* __restrict__ bias,
    const __nv_bfloat16* __restrict__ zin,
    const float* __restrict__ x, const float* __restrict__ y1,
    const float* __restrict__ alpha1_p, const float* __restrict__ alpha2_p,
    float* __restrict__ out)
{
    const float alpha = alpha2_p[0];
    const float* y = (alpha1_p[0] == 0.0f) ? x : y1;

    const int b  = blockIdx.z;
    const int mi = blockIdx.x & 1;
    const int pi = blockIdx.x >> 1;
    const int m0 = mi * 128, p0 = pi * 64;
    const int t = threadIdx.x, lane = t & 31, w = t >> 5;

    if (alpha == 0.0f) {                   // identity: copy this tile
        const float* yt = y + ((size_t)b * CIN + m0) * HW + p0;
        float* ot = out + ((size_t)b * CIN + m0) * HW + p0;
        #pragma unroll
        for (int i = 0; i < 8; i++) {
            int fi = i * 256 + t;
            int o = fi >> 4, q = (fi & 15) * 4;
            *(float4*)&ot[(size_t)o * HW + q] = *(const float4*)&yt[(size_t)o * HW + q];
        }
        return;
    }

    extern __shared__ unsigned smw[];
    unsigned* Wsp = smw;                   // [2][128][20]
    unsigned* Xs  = smw + 2 * 128 * 20;    // [64][132]
    const unsigned wba = (unsigned)__cvta_generic_to_shared(Wsp);
    const unsigned xba = (unsigned)__cvta_generic_to_shared(Xs);

    const int wm = w >> 1, wn = w & 1;     // 4 m-groups x 2 n-groups
    const int g4 = lane >> 2, tg = lane & 3;

    float acc[2][4][4];
    #pragma unroll
    for (int i = 0; i < 2; i++)
        #pragma unroll
        for (int j = 0; j < 4; j++)
            #pragma unroll
            for (int q = 0; q < 4; q++) acc[i][j][q] = 0.f;

    const unsigned* zb = (const unsigned*)zin + (size_t)b * HW * 128 + (size_t)p0 * 128;

    auto issueX = [&]() {                  // 64 pix x 128 u32 panel
        #pragma unroll
        for (int i = 0; i < 8; i++) {
            int fi = i * 256 + t, p = fi >> 5, seg = fi & 31;
            cp16(xba + (unsigned)(p * 132 + seg * 4) * 4u, zb + (size_t)p * 128 + seg * 4);
        }
    };
    auto issueW = [&](int c, int buf) {    // W chunk: 128 rows x 16 u32
        unsigned dst = wba + (unsigned)(buf * 128 * 20) * 4u;
        #pragma unroll
        for (int i = 0; i < 2; i++) {
            int fi = i * 256 + t, o = fi >> 2, seg = fi & 3;
            cp16(dst + (unsigned)(o * 20 + seg * 4) * 4u,
                 g_wbf + (size_t)(m0 + o) * 128 + c * 16 + seg * 4);
        }
        cp_commit();
    };

    issueX();
    issueW(0, 0);                          // group = X + W0
    cp_wait0(); __syncthreads();

    for (int c = 0; c < 8; c++) {
        if (c < 7) issueW(c + 1, (c + 1) & 1);
        const unsigned* Wd = Wsp + (c & 1) * 128 * 20;
        #pragma unroll
        for (int ks = 0; ks < 2; ks++) {
            unsigned a[2][4];
            int col = ks * 8 + tg;
            #pragma unroll
            for (int mt = 0; mt < 2; mt++) {
                int r = wm * 32 + mt * 16 + g4;
                a[mt][0] = Wd[r * 20 + col];
                a[mt][1] = Wd[(r + 8) * 20 + col];
                a[mt][2] = Wd[r * 20 + col + 4];
                a[mt][3] = Wd[(r + 8) * 20 + col + 4];
            }
            #pragma unroll
            for (int nt = 0; nt < 4; nt++) {
                int p = wn * 32 + nt * 8 + g4;
                unsigned b0 = Xs[p * 132 + c * 16 + col];
                unsigned b1 = Xs[p * 132 + c * 16 + col + 4];
                mma_bf16(acc[0][nt], a[0], b0, b1);
                mma_bf16(acc[1][nt], a[1], b0, b1);
            }
        }
        if (c < 7) { cp_wait0(); __syncthreads(); }
    }

    #pragma unroll
    for (int mt = 0; mt < 2; mt++) {
        int o0 = m0 + wm * 32 + mt * 16 + g4;
        float bs0 = bias[o0], bs1 = bias[o0 + 8];
        const float* yr0 = y + ((size_t)b * CIN + o0) * HW + p0;
        const float* yr1 = y + ((size_t)b * CIN + o0 + 8) * HW + p0;
        float* ob0 = out + ((size_t)b * CIN + o0) * HW + p0;
        float* ob1 = out + ((size_t)b * CIN + o0 + 8) * HW + p0;
        #pragma unroll
        for (int nt = 0; nt < 4; nt++) {
            int p = wn * 32 + nt * 8 + tg * 2;
            float2 yv0 = *(const float2*)&yr0[p];
            float2 yv1 = *(const float2*)&yr1[p];
            float2 v0 = make_float2(alpha * (acc[mt][nt][0] + bs0) + yv0.x,
                                    alpha * (acc[mt][nt][1] + bs0) + yv0.y);
            float2 v1 = make_float2(alpha * (acc[mt][nt][2] + bs1) + yv1.x,
                                    alpha * (acc[mt][nt][3] + bs1) + yv1.y);
            *(float2*)&ob0[p] = v0;
            *(float2*)&ob1[p] = v1;
        }
    }
}

// ---------------------------------------------------------------------------
// Stage-1 general path kernels (skipped when alpha1==0)
// ---------------------------------------------------------------------------
template<int MTILE>
__global__ void __launch_bounds__(256) conv1x1_tc(
    const float* __restrict__ W, const float* __restrict__ bias,
    const float* __restrict__ inA, const float* __restrict__ inB,
    const float* __restrict__ sel, const float* __restrict__ guard,
    float* __restrict__ out, int M)
{
    if (guard[0] == 0.0f) return;
    const float* in = (sel[0] == 0.0f) ? inA : inB;

    constexpr int WNT = 8 / (MTILE / 32);
    constexpr int NW  = 128 / WNT;
    constexpr int NT8 = NW / 8;
    constexpr int WLD = MTILE * 32 / 4 / 256;

    const int Mtiles = M / MTILE;
    const int b  = blockIdx.z;
    const int mi = blockIdx.x % Mtiles;
    const int pi = blockIdx.x / Mtiles;
    const int m0 = mi * MTILE, p0 = pi * 128;

    __shared__ __align__(16) float Ws[MTILE][36];
    __shared__ __align__(16) float Xs[32][136];

    const int t = threadIdx.x, lane = t & 31, w = t >> 5;
    const int wm = w / WNT, wn = w % WNT;
    const int g4 = lane >> 2, tg = lane & 3;

    float acc[2][NT8][4];
    #pragma unroll
    for (int i = 0; i < 2; i++)
        #pragma unroll
        for (int j = 0; j < NT8; j++)
            #pragma unroll
            for (int q = 0; q < 4; q++) acc[i][j][q] = 0.f;

    const float* inb = in + (size_t)b * CIN * HW + p0;
    float4 wreg[WLD], xreg[4];

    auto loadW = [&](int k0) {
        #pragma unroll
        for (int i = 0; i < WLD; i++) {
            int fi = i * 256 + t, o = fi >> 3, k4 = (fi & 7) * 4;
            wreg[i] = *(const float4*)&W[(m0 + o) * CIN + k0 + k4];
        }
    };
    auto loadX = [&](int k0) {
        #pragma unroll
        for (int i = 0; i < 4; i++) {
            int fi = i * 256 + t, k = fi >> 5, p4 = (fi & 31) * 4;
            xreg[i] = *(const float4*)&inb[(size_t)(k0 + k) * HW + p4];
        }
    };
    auto storeW = [&]() {
        #pragma unroll
        for (int i = 0; i < WLD; i++) {
            int fi = i * 256 + t, o = fi >> 3, k4 = (fi & 7) * 4;
            float4 v = wreg[i];
            Ws[o][k4 + 0] = __uint_as_float(f2tf(v.x));
            Ws[o][k4 + 1] = __uint_as_float(f2tf(v.y));
            Ws[o][k4 + 2] = __uint_as_float(f2tf(v.z));
            Ws[o][k4 + 3] = __uint_as_float(f2tf(v.w));
        }
    };
    auto storeX = [&]() {
        #pragma unroll
        for (int i = 0; i < 4; i++) {
            int fi = i * 256 + t, k = fi >> 5, p4 = (fi & 31) * 4;
            float4 v = xreg[i];
            Xs[k][p4 + 0] = __uint_as_float(f2tf(v.x));
            Xs[k][p4 + 1] = __uint_as_float(f2tf(v.y));
            Xs[k][p4 + 2] = __uint_as_float(f2tf(v.z));
            Xs[k][p4 + 3] = __uint_as_float(f2tf(v.w));
        }
    };

    loadW(0); loadX(0);
    storeW(); storeX();
    __syncthreads();

    for (int c = 0; c < 8; c++) {
        if (c < 7) { loadW((c + 1) * 32); loadX((c + 1) * 32); }
        #pragma unroll
        for (int ks = 0; ks < 4; ks++) {
            unsigned a[2][4];
            #pragma unroll
            for (int mt = 0; mt < 2; mt++) {
                int r = wm * 32 + mt * 16 + g4, col = ks * 8 + tg;
                a[mt][0] = __float_as_uint(Ws[r][col]);
                a[mt][1] = __float_as_uint(Ws[r + 8][col]);
                a[mt][2] = __float_as_uint(Ws[r][col + 4]);
                a[mt][3] = __float_as_uint(Ws[r + 8][col + 4]);
            }
            #pragma unroll
            for (int nt = 0; nt < NT8; nt++) {
                int p = wn * NW + nt * 8 + g4;
                unsigned b0 = __float_as_uint(Xs[ks * 8 + tg][p]);
                unsigned b1 = __float_as_uint(Xs[ks * 8 + 4 + tg][p]);
                mma_tf32(acc[0][nt], a[0], b0, b1);
                mma_tf32(acc[1][nt], a[1], b0, b1);
            }
        }
        __syncthreads();
        if (c < 7) { storeW(); storeX(); __syncthreads(); }
    }

    #pragma unroll
    for (int mt = 0; mt < 2; mt++) {
        int o0 = m0 + wm * 32 + mt * 16 + g4;
        float bs0 = bias[o0], bs1 = bias[o0 + 8];
        #pragma unroll
        for (int nt = 0; nt < NT8; nt++) {
            int p = p0 + wn * NW + nt * 8 + tg * 2;
            float2 v0 = make_float2(acc[mt][nt][0] + bs0, acc[mt][nt][1] + bs0);
            float2 v1 = make_float2(acc[mt][nt][2] + bs1, acc[mt][nt][3] + bs1);
            *(float2*)&out[((size_t)b * M + o0) * HW + p]     = v0;
            *(float2*)&out[((size_t)b * M + o0 + 8) * HW + p] = v1;
        }
    }
}

__global__ void __launch_bounds__(256) attn_s1(
    const float* __restrict__ x, const float* __restrict__ fbc,
    const float* __restrict__ fd, const float* __restrict__ alpha_p,
    float* __restrict__ y1)
{
    const float alpha = alpha_p[0];
    if (alpha == 0.0f) return;
    extern __shared__ float sm1f[];
    float* fbc_s = sm1f;
    float* fdc_s = fbc_s + 64 * 256;
    __nv_bfloat16* A_s = (__nv_bfloat16*)(fdc_s + 16 * 260);

    const int beta = blockIdx.x;
    const int n  = beta >> 6;
    const int ph = (beta >> 3) & 7, pw = beta & 7;
    const int t = threadIdx.x;

    for (int idx = t; idx < 64 * 256; idx += 256) {
        int r = idx >> 8, j = idx & 255;
        fbc_s[r * 256 + j] = fbc[(n * 64 + r) * HW + ((j >> 4) * 8 + ph) * 128 + (j & 15) * 8 + pw];
    }
    __syncthreads();

    float fbl[32];
    #pragma unroll
    for (int k = 0; k < 32; k++) fbl[k] = fbc_s[k * 256 + t];

    float mx = -1e30f, den = 0.f;
    for (int m = 0; m < 256; m++) {
        float s = 0.f;
        #pragma unroll
        for (int k = 0; k < 32; k++) s += fbl[k] * fbc_s[(32 + k) * 256 + m];
        if (s > mx) { den *= __expf(mx - s); mx = s; }
        den += __expf(s - mx);
    }
    float inv = 1.0f / den;
    for (int m = 0; m < 256; m++) {
        float s = 0.f;
        #pragma unroll
        for (int k = 0; k < 32; k++) s += fbl[k] * fbc_s[(32 + k) * 256 + m];
        A_s[t * 258 + m] = __float2bfloat16(__expf(s - mx) * inv);
    }
    __syncthreads();

    for (int cc = 0; cc < 16; cc++) {
        for (int idx = t; idx < 16 * 256; idx += 256) {
            int c = idx >> 8, j = idx & 255;
            fdc_s[c * 260 + j] = fd[(n * CIN + cc * 16 + c) * HW +
                                    ((j >> 4) * 8 + ph) * 128 + (j & 15) * 8 + pw];
        }
        __syncthreads();
        float acc[16] = {};
        for (int m = 0; m < 256; m++) {
            float a = __bfloat162float(A_s[t * 258 + m]);
            #pragma unroll
            for (int c = 0; c < 16; c++) acc[c] += a * fdc_s[c * 260 + m];
        }
        const int pix = ((t >> 4) * 8 + ph) * 128 + (t & 15) * 8 + pw;
        #pragma unroll
        for (int c = 0; c < 16; c++) {
            int off = (n * CIN + cc * 16 + c) * HW + pix;
            y1[off] = alpha * acc[c] + x[off];
        }
        __syncthreads();
    }
}

// ---------------------------------------------------------------------------
// Host launcher — 6 launches total
// ---------------------------------------------------------------------------
extern "C" void kernel_launch(void* const* d_in, const int* in_sizes, int n_in,
                              void* d_out, int out_size)
{
    const float* x      = (const float*)d_in[0];
    const float* Wb1    = (const float*)d_in[1];
    const float* bb1    = (const float*)d_in[2];
    const float* Wc1    = (const float*)d_in[3];
    const float* bc1    = (const float*)d_in[4];
    const float* Wd1    = (const float*)d_in[5];
    const float* bd1    = (const float*)d_in[6];
    const float* alpha1 = (const float*)d_in[7];
    const float* Wb2    = (const float*)d_in[8];
    const float* bb2    = (const float*)d_in[9];
    const float* Wc2    = (const float*)d_in[10];
    const float* bc2    = (const float*)d_in[11];
    const float* Wd2    = (const float*)d_in[12];
    const float* bd2    = (const float*)d_in[13];
    const float* alpha2 = (const float*)d_in[14];
    float* out = (float*)d_out;

    cudaFuncSetAttribute(attn_s1, cudaFuncAttributeMaxDynamicSharedMemorySize, 214272);
    cudaFuncSetAttribute(attn_zhat, cudaFuncAttributeMaxDynamicSharedMemorySize, ZA_TOT * 4);
    cudaFuncSetAttribute(conv_fbc_tc, cudaFuncAttributeMaxDynamicSharedMemorySize, FBC_SMEM);
    cudaFuncSetAttribute(conv_fe_bf, cudaFuncAttributeMaxDynamicSharedMemorySize, FE_SMEM);

    float *y1p, *fdp, *fbcp;
    cudaGetSymbolAddress((void**)&y1p,  g_y1);
    cudaGetSymbolAddress((void**)&fdp,  g_fd);
    cudaGetSymbolAddress((void**)&fbcp, g_fbc);

    // ---- Stage 1 (general path; all kernels self-skip when alpha1==0) ---
    conv_fbc_tc<<<dim3(128, 1, 8), 256, FBC_SMEM>>>(
        Wb1, bb1, Wc1, bc1, x, x, alpha1, alpha1, Wd1, fbcp);
    conv1x1_tc<128><<<dim3(256, 1, NIMG), 256>>>(Wd1, bd1, x, x, alpha1, alpha1, fdp, 256);
    attn_s1<<<512, 256, 214272>>>(x, fbcp, fdp, alpha1, y1p);

    // ---- Stage 2 (z==8 slice of conv_fbc packs Wd2 -> g_wbf) -------------
    conv_fbc_tc<<<dim3(128, 1, 9), 256, FBC_SMEM>>>(
        Wb2, bb2, Wc2, bc2, x, y1p, alpha1, alpha2, Wd2, fbcp);
    attn_zhat<<<2048, 256, ZA_TOT * 4>>>(x, y1p, fbcp, alpha1, alpha2, (__nv_bfloat16*)fdp);
    conv_fe_bf<<<dim3(512, 1, NIMG), 256, FE_SMEM>>>(bd2, (const __nv_bfloat16*)fdp,
                                                     x, y1p, alpha1, alpha2, out);
}

// round 14
// speedup vs baseline: 1.0260x; 1.0260x over previous
#include <cuda_runtime.h>
#include <cuda_bf16.h>

#define NIMG 8
#define CIN  256
#define HW   16384      // 128*128
#define C8   32

// ---------------------------------------------------------------------------
// Scratch
// ---------------------------------------------------------------------------
__device__ float    g_y1 [NIMG * CIN * HW];
__device__ float    g_fd [NIMG * CIN * HW];   // stage-1 fd / stage-2 zhat (bf16 view)
__device__ float    g_fbc[NIMG * 64  * HW];
__device__ unsigned g_wbf[CIN * 128];         // Wd2 as bf16 pairs [o][k/2]

// ---------------------------------------------------------------------------
// Helpers
// ---------------------------------------------------------------------------
__device__ __forceinline__ unsigned f2tf(float f) {
    unsigned u; asm("cvt.rna.tf32.f32 %0, %1;" : "=r"(u) : "f"(f)); return u;
}
__device__ __forceinline__ void mma_tf32(float* c, const unsigned* a, unsigned b0, unsigned b1) {
    asm volatile("mma.sync.aligned.m16n8k8.row.col.f32.tf32.tf32.f32 "
                 "{%0,%1,%2,%3}, {%4,%5,%6,%7}, {%8,%9}, {%0,%1,%2,%3};"
                 : "+f"(c[0]), "+f"(c[1]), "+f"(c[2]), "+f"(c[3])
                 : "r"(a[0]), "r"(a[1]), "r"(a[2]), "r"(a[3]), "r"(b0), "r"(b1));
}
__device__ __forceinline__ void mma_bf16(float* c, const unsigned* a, unsigned b0, unsigned b1) {
    asm volatile("mma.sync.aligned.m16n8k16.row.col.f32.bf16.bf16.f32 "
                 "{%0,%1,%2,%3}, {%4,%5,%6,%7}, {%8,%9}, {%0,%1,%2,%3};"
                 : "+f"(c[0]), "+f"(c[1]), "+f"(c[2]), "+f"(c[3])
                 : "r"(a[0]), "r"(a[1]), "r"(a[2]), "r"(a[3]), "r"(b0), "r"(b1));
}
__device__ __forceinline__ unsigned pkbf(float lo, float hi) {
    __nv_bfloat162 h = __floats2bfloat162_rn(lo, hi);
    return *(unsigned*)&h;
}
__device__ __forceinline__ void cp16(unsigned dst, const void* src) {
    asm volatile("cp.async.cg.shared.global [%0], [%1], 16;" :: "r"(dst), "l"(src));
}
__device__ __forceinline__ void cp_commit() { asm volatile("cp.async.commit_group;"); }
__device__ __forceinline__ void cp_wait0()  { asm volatile("cp.async.wait_group 0;"); }

__device__ __forceinline__ unsigned smem_u32(const void* p) {
    unsigned a;
    asm("{ .reg .u64 t; cvta.to.shared.u64 t, %1; cvt.u32.u64 %0, t; }" : "=r"(a) : "l"(p));
    return a;
}

// ===========================================================================
// conv_fbc_tc: fbc = [Wb;Wc].in + [bb;bc]   (M=64, tf32)
// BOTH operands via cp.async (raw fp32; tf32 mma truncates). Double-buffered.
// grid z==8 blocks (stage-2 only) pack Wfe -> g_wbf (bf16 pairs).
// ===========================================================================
#define FBC_SMEM ((2 * 64 * 36 + 2 * 32 * 136) * 4)

__global__ void __launch_bounds__(256, 3) conv_fbc_tc(
    const float* __restrict__ Wb, const float* __restrict__ bb,
    const float* __restrict__ Wc, const float* __restrict__ bc,
    const float* __restrict__ inA, const float* __restrict__ inB,
    const float* __restrict__ sel, const float* __restrict__ guard,
    const float* __restrict__ Wfe,
    float* __restrict__ out)
{
    if (guard[0] == 0.0f) return;

    if (blockIdx.z == 8) {                 // folded wcvt
        int idx = blockIdx.x * 256 + threadIdx.x;
        int o = idx >> 7, kp = idx & 127;
        g_wbf[idx] = pkbf(Wfe[o * 256 + kp * 2], Wfe[o * 256 + kp * 2 + 1]);
        return;
    }

    const float* in = (sel[0] == 0.0f) ? inA : inB;
    const int b = blockIdx.z, p0 = blockIdx.x * 128;

    extern __shared__ float smf[];
    float* Wbuf = smf;
    float* Xbuf = smf + 2 * 64 * 36;
    const unsigned wba = smem_u32(Wbuf);
    const unsigned xba = smem_u32(Xbuf);

    const int t = threadIdx.x, lane = t & 31, w = t >> 5;
    const int wm = w >> 2, wn = w & 3;
    const int g4 = lane >> 2, tg = lane & 3;

    float acc[2][4][4] = {};
    const float* inb = in + (size_t)b * CIN * HW + p0;

    auto issue = [&](int k0, int buf) {
        unsigned wd = wba + (unsigned)(buf * 64 * 36) * 4u;
        #pragma unroll
        for (int i = 0; i < 2; i++) {
            int fi = i * 256 + t, o = fi >> 3, k4 = (fi & 7) * 4;
            const float* src = (o < 32) ? &Wb[o * 256 + k0 + k4]
                                        : &Wc[(o - 32) * 256 + k0 + k4];
            cp16(wd + (unsigned)(o * 36 + k4) * 4u, src);
        }
        unsigned xd = xba + (unsigned)(buf * 32 * 136) * 4u;
        #pragma unroll
        for (int i = 0; i < 4; i++) {
            int fi = i * 256 + t, k = fi >> 5, seg = fi & 31;
            cp16(xd + (unsigned)(k * 136 + seg * 4) * 4u,
                 inb + (size_t)(k0 + k) * HW + seg * 4);
        }
        cp_commit();
    };

    issue(0, 0);
    cp_wait0(); __syncthreads();

    for (int c = 0; c < 8; c++) {
        if (c < 7) issue((c + 1) * 32, (c + 1) & 1);
        const float* Wd = Wbuf + (c & 1) * 64 * 36;
        const float* Xd = Xbuf + (c & 1) * 32 * 136;
        #pragma unroll
        for (int ks = 0; ks < 4; ks++) {
            unsigned a[2][4];
            int col = ks * 8 + tg;
            #pragma unroll
            for (int mt = 0; mt < 2; mt++) {
                int r = wm * 32 + mt * 16 + g4;
                a[mt][0] = __float_as_uint(Wd[r * 36 + col]);
                a[mt][1] = __float_as_uint(Wd[(r + 8) * 36 + col]);
                a[mt][2] = __float_as_uint(Wd[r * 36 + col + 4]);
                a[mt][3] = __float_as_uint(Wd[(r + 8) * 36 + col + 4]);
            }
            #pragma unroll
            for (int nt = 0; nt < 4; nt++) {
                int p = wn * 32 + nt * 8 + g4;
                unsigned b0 = __float_as_uint(Xd[(ks * 8 + tg) * 136 + p]);
                unsigned b1 = __float_as_uint(Xd[(ks * 8 + 4 + tg) * 136 + p]);
                mma_tf32(acc[0][nt], a[0], b0, b1);
                mma_tf32(acc[1][nt], a[1], b0, b1);
            }
        }
        if (c < 7) { cp_wait0(); __syncthreads(); }
    }

    #pragma unroll
    for (int mt = 0; mt < 2; mt++) {
        int o0 = wm * 32 + mt * 16 + g4, o1 = o0 + 8;
        float bs0 = (o0 < 32) ? bb[o0] : bc[o0 - 32];
        float bs1 = (o1 < 32) ? bb[o1] : bc[o1 - 32];
        #pragma unroll
        for (int nt = 0; nt < 4; nt++) {
            int p = p0 + wn * 32 + nt * 8 + tg * 2;
            *(float2*)&out[((size_t)b * 64 + o0) * HW + p] =
                make_float2(acc[mt][nt][0] + bs0, acc[mt][nt][1] + bs0);
            *(float2*)&out[((size_t)b * 64 + o1) * HW + p] =
                make_float2(acc[mt][nt][2] + bs1, acc[mt][nt][3] + bs1);
        }
    }
}

// ===========================================================================
// attn_zhat (occ 3): logits(fp32)+softmax, zhat = A.y^T bf16 -> [n][pix][256c]
// ===========================================================================
#define ZA_YS  0
#define ZA_FB  (256 * 36)
#define ZA_AS  (ZA_FB + 64 * 68)
#define ZA_TOT (ZA_AS + 64 * 36)

__global__ void __launch_bounds__(256, 3) attn_zhat(
    const float* __restrict__ x, const float* __restrict__ y1,
    const float* __restrict__ fbc,
    const float* __restrict__ alpha1_p, const float* __restrict__ alpha2_p,
    __nv_bfloat16* __restrict__ zout)
{
    if (alpha2_p[0] == 0.0f) return;
    const float* y = (alpha1_p[0] == 0.0f) ? x : y1;

    extern __shared__ unsigned smu[];
    unsigned* ysp = smu + ZA_YS;
    float*    fb  = (float*)(smu + ZA_FB);
    unsigned* Asp = smu + ZA_AS;
    unsigned* zh  = smu + ZA_YS;

    const int beta = blockIdx.x;
    const int n  = beta >> 8;
    const int qh = (beta >> 4) & 15, qw = beta & 15;
    const int base = (qh * 8) * 128 + qw * 8;
    const int t = threadIdx.x, lane = t & 31, w = t >> 5;
    const int g4 = lane >> 2, tg = lane & 3;

    {
        const float* fbb = fbc + (size_t)n * 64 * HW + base;
        #pragma unroll
        for (int i = 0; i < 4; i++) {
            int fi = i * 256 + t;
            int r = fi >> 4, jr = (fi >> 1) & 7, jc = (fi & 1) * 4;
            *(float4*)&fb[r * 68 + jr * 8 + jc] = *(const float4*)&fbb[(size_t)r * HW + jr * 128 + jc];
        }
        const float* yb = y + (size_t)n * CIN * HW + base;
        #pragma unroll
        for (int i = 0; i < 16; i++) {
            int fi = i * 256 + t;
            int c = fi >> 4, jr = (fi >> 1) & 7, jc = (fi & 1) * 4;
            float4 v = *(const float4*)&yb[(size_t)c * HW + jr * 128 + jc];
            int j0 = jr * 4 + (jc >> 1);
            uint2 pk = make_uint2(pkbf(v.x, v.y), pkbf(v.z, v.w));
            *(uint2*)&ysp[c * 36 + j0] = pk;
        }
    }
    __syncthreads();

    {   // logits + softmax (fp32)
        const int l = t >> 2, mq = t & 3;
        float fbl[32];
        #pragma unroll
        for (int k = 0; k < 32; k++) fbl[k] = fb[k * 68 + l];
        float s[16];
        #pragma unroll
        for (int mm = 0; mm < 16; mm++) {
            int m = mq * 16 + mm;
            float v = 0.f;
            #pragma unroll
            for (int k = 0; k < 32; k++) v += fbl[k] * fb[(32 + k) * 68 + m];
            s[mm] = v;
        }
        float mx = -1e30f;
        #pragma unroll
        for (int i = 0; i < 16; i++) mx = fmaxf(mx, s[i]);
        mx = fmaxf(mx, __shfl_xor_sync(0xffffffff, mx, 1));
        mx = fmaxf(mx, __shfl_xor_sync(0xffffffff, mx, 2));
        float sum = 0.f;
        #pragma unroll
        for (int i = 0; i < 16; i++) { s[i] = __expf(s[i] - mx); sum += s[i]; }
        sum += __shfl_xor_sync(0xffffffff, sum, 1);
        sum += __shfl_xor_sync(0xffffffff, sum, 2);
        float inv = 1.0f / sum;
        #pragma unroll
        for (int q = 0; q < 8; q++)
            Asp[l * 36 + mq * 8 + q] = pkbf(s[2 * q] * inv, s[2 * q + 1] * inv);
    }
    __syncthreads();

    {   // zhat = A . y^T  (M64 l, N256 c, K64 m), bf16
        const int wm = w >> 2, wc = w & 3;
        const int m0 = wm * 32, c0w = wc * 64;
        float acc[2][8][4];
        #pragma unroll
        for (int i = 0; i < 2; i++)
            #pragma unroll
            for (int j = 0; j < 8; j++)
                #pragma unroll
                for (int q = 0; q < 4; q++) acc[i][j][q] = 0.f;
        #pragma unroll
        for (int ks = 0; ks < 4; ks++) {
            unsigned a[2][4];
            int col = ks * 8 + tg;
            #pragma unroll
            for (int mt = 0; mt < 2; mt++) {
                int r = m0 + mt * 16 + g4;
                a[mt][0] = Asp[r * 36 + col];
                a[mt][1] = Asp[(r + 8) * 36 + col];
                a[mt][2] = Asp[r * 36 + col + 4];
                a[mt][3] = Asp[(r + 8) * 36 + col + 4];
            }
            #pragma unroll
            for (int nt = 0; nt < 8; nt++) {
                int c = c0w + nt * 8 + g4;
                unsigned b0 = ysp[c * 36 + col];
                unsigned b1 = ysp[c * 36 + col + 4];
                mma_bf16(acc[0][nt], a[0], b0, b1);
                mma_bf16(acc[1][nt], a[1], b0, b1);
            }
        }
        __syncthreads();                       // ysp reads done -> zh alias safe
        #pragma unroll
        for (int mt = 0; mt < 2; mt++) {
            int l0 = m0 + mt * 16 + g4;
            #pragma unroll
            for (int nt = 0; nt < 8; nt++) {
                int cp = wc * 32 + nt * 4 + tg;
                zh[l0 * 132 + cp]       = pkbf(acc[mt][nt][0], acc[mt][nt][1]);
                zh[(l0 + 8) * 132 + cp] = pkbf(acc[mt][nt][2], acc[mt][nt][3]);
            }
        }
    }
    __syncthreads();

    {   // coalesced global write: [pix][c] bf16
        unsigned* zb = (unsigned*)zout + (size_t)n * HW * 128;
        #pragma unroll
        for (int i = 0; i < 32; i++) {
            int fi = i * 256 + t;
            int l = fi >> 7, cq = fi & 127;
            int pix = base + (l >> 3) * 128 + (l & 7);
            zb[(size_t)pix * 128 + cq] = zh[l * 132 + cq];
        }
    }
}

// ===========================================================================
// conv_fe_bf (R11 v2): out = alpha*(Wd.zhat + bd) + y, bf16 mma.
// Full X panel resident (cp.async), W bf16 pre-packed, cp.async double-buffered.
// Dynamic SMEM: Wsp[2][128][20] | Xs[128][132]  = 88064 B, occ 2.
// ===========================================================================
#define FE_SMEM ((2 * 128 * 20 + 128 * 132) * 4)

__global__ void __launch_bounds__(256, 2) conv_fe_bf(
    const float* __restrict__ bias,
    const __nv_bfloat16* __restrict__ zin,
    const float* __restrict__ x, const float* __restrict__ y1,
    const float* __restrict__ alpha1_p, const float* __restrict__ alpha2_p,
    float* __restrict__ out)
{
    const float alpha = alpha2_p[0];
    const float* y = (alpha1_p[0] == 0.0f) ? x : y1;

    const int b  = blockIdx.z;
    const int mi = blockIdx.x & 1;
    const int pi = blockIdx.x >> 1;
    const int m0 = mi * 128, p0 = pi * 128;
    const int t = threadIdx.x, lane = t & 31, w = t >> 5;

    if (alpha == 0.0f) {                   // identity: copy this tile
        const float* yt = y + ((size_t)b * CIN + m0) * HW + p0;
        float* ot = out + ((size_t)b * CIN + m0) * HW + p0;
        #pragma unroll
        for (int i = 0; i < 16; i++) {
            int fi = i * 256 + t;
            int o = fi >> 5, q = (fi & 31) * 4;
            *(float4*)&ot[(size_t)o * HW + q] = *(const float4*)&yt[(size_t)o * HW + q];
        }
        return;
    }

    extern __shared__ unsigned smw[];
    unsigned* Wsp = smw;                   // [2][128][20]
    unsigned* Xs  = smw + 2 * 128 * 20;    // [128][132]
    const unsigned wba = smem_u32(Wsp);
    const unsigned xba = smem_u32(Xs);

    const int wm = w >> 1, wn = w & 1;
    const int g4 = lane >> 2, tg = lane & 3;

    float acc[2][8][4];
    #pragma unroll
    for (int i = 0; i < 2; i++)
        #pragma unroll
        for (int j = 0; j < 8; j++)
            #pragma unroll
            for (int q = 0; q < 4; q++) acc[i][j][q] = 0.f;

    const unsigned* zb = (const unsigned*)zin + (size_t)b * HW * 128 + (size_t)p0 * 128;

    auto issueX = [&]() {                  // full 128x128-u32 panel
        #pragma unroll
        for (int i = 0; i < 16; i++) {
            int fi = i * 256 + t, p = fi >> 5, seg = fi & 31;
            cp16(xba + (unsigned)(p * 132 + seg * 4) * 4u, zb + (size_t)p * 128 + seg * 4);
        }
    };
    auto issueW = [&](int c, int buf) {    // W chunk: 128 rows x 16 u32
        unsigned dst = wba + (unsigned)(buf * 128 * 20) * 4u;
        #pragma unroll
        for (int i = 0; i < 2; i++) {
            int fi = i * 256 + t, o = fi >> 2, seg = fi & 3;
            cp16(dst + (unsigned)(o * 20 + seg * 4) * 4u,
                 g_wbf + (size_t)(m0 + o) * 128 + c * 16 + seg * 4);
        }
        cp_commit();
    };

    issueX();
    issueW(0, 0);                          // group contains X + W0
    cp_wait0(); __syncthreads();

    for (int c = 0; c < 8; c++) {
        if (c < 7) issueW(c + 1, (c + 1) & 1);
        const unsigned* Wd = Wsp + (c & 1) * 128 * 20;
        #pragma unroll
        for (int ks = 0; ks < 2; ks++) {
            unsigned a[2][4];
            int col = ks * 8 + tg;
            #pragma unroll
            for (int mt = 0; mt < 2; mt++) {
                int r = wm * 32 + mt * 16 + g4;
                a[mt][0] = Wd[r * 20 + col];
                a[mt][1] = Wd[(r + 8) * 20 + col];
                a[mt][2] = Wd[r * 20 + col + 4];
                a[mt][3] = Wd[(r + 8) * 20 + col + 4];
            }
            #pragma unroll
            for (int nt = 0; nt < 8; nt++) {
                int p = wn * 64 + nt * 8 + g4;
                unsigned b0 = Xs[p * 132 + c * 16 + col];
                unsigned b1 = Xs[p * 132 + c * 16 + col + 4];
                mma_bf16(acc[0][nt], a[0], b0, b1);
                mma_bf16(acc[1][nt], a[1], b0, b1);
            }
        }
        if (c < 7) { cp_wait0(); __syncthreads(); }
    }

    #pragma unroll
    for (int mt = 0; mt < 2; mt++) {
        int o0 = m0 + wm * 32 + mt * 16 + g4;
        float bs0 = bias[o0], bs1 = bias[o0 + 8];
        const float* yr0 = y + ((size_t)b * CIN + o0) * HW + p0;
        const float* yr1 = y + ((size_t)b * CIN + o0 + 8) * HW + p0;
        float* ob0 = out + ((size_t)b * CIN + o0) * HW + p0;
        float* ob1 = out + ((size_t)b * CIN + o0 + 8) * HW + p0;
        #pragma unroll
        for (int nt = 0; nt < 8; nt++) {
            int p = wn * 64 + nt * 8 + tg * 2;
            float2 yv0 = *(const float2*)&yr0[p];
            float2 yv1 = *(const float2*)&yr1[p];
            float2 v0 = make_float2(alpha * (acc[mt][nt][0] + bs0) + yv0.x,
                                    alpha * (acc[mt][nt][1] + bs0) + yv0.y);
            float2 v1 = make_float2(alpha * (acc[mt][nt][2] + bs1) + yv1.x,
                                    alpha * (acc[mt][nt][3] + bs1) + yv1.y);
            *(float2*)&ob0[p] = v0;
            *(float2*)&ob1[p] = v1;
        }
    }
}

// ---------------------------------------------------------------------------
// Stage-1 general path kernels (skipped when alpha1==0)
// ---------------------------------------------------------------------------
template<int MTILE>
__global__ void __launch_bounds__(256) conv1x1_tc(
    const float* __restrict__ W, const float* __restrict__ bias,
    const float* __restrict__ inA, const float* __restrict__ inB,
    const float* __restrict__ sel, const float* __restrict__ guard,
    float* __restrict__ out, int M)
{
    if (guard[0] == 0.0f) return;
    const float* in = (sel[0] == 0.0f) ? inA : inB;

    constexpr int WNT = 8 / (MTILE / 32);
    constexpr int NW  = 128 / WNT;
    constexpr int NT8 = NW / 8;
    constexpr int WLD = MTILE * 32 / 4 / 256;

    const int Mtiles = M / MTILE;
    const int b  = blockIdx.z;
    const int mi = blockIdx.x % Mtiles;
    const int pi = blockIdx.x / Mtiles;
    const int m0 = mi * MTILE, p0 = pi * 128;

    __shared__ __align__(16) float Ws[MTILE][36];
    __shared__ __align__(16) float Xs[32][136];

    const int t = threadIdx.x, lane = t & 31, w = t >> 5;
    const int wm = w / WNT, wn = w % WNT;
    const int g4 = lane >> 2, tg = lane & 3;

    float acc[2][NT8][4];
    #pragma unroll
    for (int i = 0; i < 2; i++)
        #pragma unroll
        for (int j = 0; j < NT8; j++)
            #pragma unroll
            for (int q = 0; q < 4; q++) acc[i][j][q] = 0.f;

    const float* inb = in + (size_t)b * CIN * HW + p0;
    float4 wreg[WLD], xreg[4];

    auto loadW = [&](int k0) {
        #pragma unroll
        for (int i = 0; i < WLD; i++) {
            int fi = i * 256 + t, o = fi >> 3, k4 = (fi & 7) * 4;
            wreg[i] = *(const float4*)&W[(m0 + o) * CIN + k0 + k4];
        }
    };
    auto loadX = [&](int k0) {
        #pragma unroll
        for (int i = 0; i < 4; i++) {
            int fi = i * 256 + t, k = fi >> 5, p4 = (fi & 31) * 4;
            xreg[i] = *(const float4*)&inb[(size_t)(k0 + k) * HW + p4];
        }
    };
    auto storeW = [&]() {
        #pragma unroll
        for (int i = 0; i < WLD; i++) {
            int fi = i * 256 + t, o = fi >> 3, k4 = (fi & 7) * 4;
            float4 v = wreg[i];
            Ws[o][k4 + 0] = __uint_as_float(f2tf(v.x));
            Ws[o][k4 + 1] = __uint_as_float(f2tf(v.y));
            Ws[o][k4 + 2] = __uint_as_float(f2tf(v.z));
            Ws[o][k4 + 3] = __uint_as_float(f2tf(v.w));
        }
    };
    auto storeX = [&]() {
        #pragma unroll
        for (int i = 0; i < 4; i++) {
            int fi = i * 256 + t, k = fi >> 5, p4 = (fi & 31) * 4;
            float4 v = xreg[i];
            Xs[k][p4 + 0] = __uint_as_float(f2tf(v.x));
            Xs[k][p4 + 1] = __uint_as_float(f2tf(v.y));
            Xs[k][p4 + 2] = __uint_as_float(f2tf(v.z));
            Xs[k][p4 + 3] = __uint_as_float(f2tf(v.w));
        }
    };

    loadW(0); loadX(0);
    storeW(); storeX();
    __syncthreads();

    for (int c = 0; c < 8; c++) {
        if (c < 7) { loadW((c + 1) * 32); loadX((c + 1) * 32); }
        #pragma unroll
        for (int ks = 0; ks < 4; ks++) {
            unsigned a[2][4];
            #pragma unroll
            for (int mt = 0; mt < 2; mt++) {
                int r = wm * 32 + mt * 16 + g4, col = ks * 8 + tg;
                a[mt][0] = __float_as_uint(Ws[r][col]);
                a[mt][1] = __float_as_uint(Ws[r + 8][col]);
                a[mt][2] = __float_as_uint(Ws[r][col + 4]);
                a[mt][3] = __float_as_uint(Ws[r + 8][col + 4]);
            }
            #pragma unroll
            for (int nt = 0; nt < NT8; nt++) {
                int p = wn * NW + nt * 8 + g4;
                unsigned b0 = __float_as_uint(Xs[ks * 8 + tg][p]);
                unsigned b1 = __float_as_uint(Xs[ks * 8 + 4 + tg][p]);
                mma_tf32(acc[0][nt], a[0], b0, b1);
                mma_tf32(acc[1][nt], a[1], b0, b1);
            }
        }
        __syncthreads();
        if (c < 7) { storeW(); storeX(); __syncthreads(); }
    }

    #pragma unroll
    for (int mt = 0; mt < 2; mt++) {
        int o0 = m0 + wm * 32 + mt * 16 + g4;
        float bs0 = bias[o0], bs1 = bias[o0 + 8];
        #pragma unroll
        for (int nt = 0; nt < NT8; nt++) {
            int p = p0 + wn * NW + nt * 8 + tg * 2;
            float2 v0 = make_float2(acc[mt][nt][0] + bs0, acc[mt][nt][1] + bs0);
            float2 v1 = make_float2(acc[mt][nt][2] + bs1, acc[mt][nt][3] + bs1);
            *(float2*)&out[((size_t)b * M + o0) * HW + p]     = v0;
            *(float2*)&out[((size_t)b * M + o0 + 8) * HW + p] = v1;
        }
    }
}

__global__ void __launch_bounds__(256) attn_s1(
    const float* __restrict__ x, const float* __restrict__ fbc,
    const float* __restrict__ fd, const float* __restrict__ alpha_p,
    float* __restrict__ y1)
{
    const float alpha = alpha_p[0];
    if (alpha == 0.0f) return;
    extern __shared__ float sm1f[];
    float* fbc_s = sm1f;
    float* fdc_s = fbc_s + 64 * 256;
    __nv_bfloat16* A_s = (__nv_bfloat16*)(fdc_s + 16 * 260);

    const int beta = blockIdx.x;
    const int n  = beta >> 6;
    const int ph = (beta >> 3) & 7, pw = beta & 7;
    const int t = threadIdx.x;

    for (int idx = t; idx < 64 * 256; idx += 256) {
        int r = idx >> 8, j = idx & 255;
        fbc_s[r * 256 + j] = fbc[(n * 64 + r) * HW + ((j >> 4) * 8 + ph) * 128 + (j & 15) * 8 + pw];
    }
    __syncthreads();

    float fbl[32];
    #pragma unroll
    for (int k = 0; k < 32; k++) fbl[k] = fbc_s[k * 256 + t];

    float mx = -1e30f, den = 0.f;
    for (int m = 0; m < 256; m++) {
        float s = 0.f;
        #pragma unroll
        for (int k = 0; k < 32; k++) s += fbl[k] * fbc_s[(32 + k) * 256 + m];
        if (s > mx) { den *= __expf(mx - s); mx = s; }
        den += __expf(s - mx);
    }
    float inv = 1.0f / den;
    for (int m = 0; m < 256; m++) {
        float s = 0.f;
        #pragma unroll
        for (int k = 0; k < 32; k++) s += fbl[k] * fbc_s[(32 + k) * 256 + m];
        A_s[t * 258 + m] = __float2bfloat16(__expf(s - mx) * inv);
    }
    __syncthreads();

    for (int cc = 0; cc < 16; cc++) {
        for (int idx = t; idx < 16 * 256; idx += 256) {
            int c = idx >> 8, j = idx & 255;
            fdc_s[c * 260 + j] = fd[(n * CIN + cc * 16 + c) * HW +
                                    ((j >> 4) * 8 + ph) * 128 + (j & 15) * 8 + pw];
        }
        __syncthreads();
        float acc[16] = {};
        for (int m = 0; m < 256; m++) {
            float a = __bfloat162float(A_s[t * 258 + m]);
            #pragma unroll
            for (int c = 0; c < 16; c++) acc[c] += a * fdc_s[c * 260 + m];
        }
        const int pix = ((t >> 4) * 8 + ph) * 128 + (t & 15) * 8 + pw;
        #pragma unroll
        for (int c = 0; c < 16; c++) {
            int off = (n * CIN + cc * 16 + c) * HW + pix;
            y1[off] = alpha * acc[c] + x[off];
        }
        __syncthreads();
    }
}

// ---------------------------------------------------------------------------
// Host launcher — 6 launches total
// ---------------------------------------------------------------------------
extern "C" void kernel_launch(void* const* d_in, const int* in_sizes, int n_in,
                              void* d_out, int out_size)
{
    const float* x      = (const float*)d_in[0];
    const float* Wb1    = (const float*)d_in[1];
    const float* bb1    = (const float*)d_in[2];
    const float* Wc1    = (const float*)d_in[3];
    const float* bc1    = (const float*)d_in[4];
    const float* Wd1    = (const float*)d_in[5];
    const float* bd1    = (const float*)d_in[6];
    const float* alpha1 = (const float*)d_in[7];
    const float* Wb2    = (const float*)d_in[8];
    const float* bb2    = (const float*)d_in[9];
    const float* Wc2    = (const float*)d_in[10];
    const float* bc2    = (const float*)d_in[11];
    const float* Wd2    = (const float*)d_in[12];
    const float* bd2    = (const float*)d_in[13];
    const float* alpha2 = (const float*)d_in[14];
    float* out = (float*)d_out;

    cudaFuncSetAttribute(attn_s1, cudaFuncAttributeMaxDynamicSharedMemorySize, 214272);
    cudaFuncSetAttribute(attn_zhat, cudaFuncAttributeMaxDynamicSharedMemorySize, ZA_TOT * 4);
    cudaFuncSetAttribute(conv_fbc_tc, cudaFuncAttributeMaxDynamicSharedMemorySize, FBC_SMEM);
    cudaFuncSetAttribute(conv_fe_bf, cudaFuncAttributeMaxDynamicSharedMemorySize, FE_SMEM);

    float *y1p, *fdp, *fbcp;
    cudaGetSymbolAddress((void**)&y1p,  g_y1);
    cudaGetSymbolAddress((void**)&fdp,  g_fd);
    cudaGetSymbolAddress((void**)&fbcp, g_fbc);

    // ---- Stage 1 (general path; all kernels self-skip when alpha1==0) ---
    conv_fbc_tc<<<dim3(128, 1, 8), 256, FBC_SMEM>>>(
        Wb1, bb1, Wc1, bc1, x, x, alpha1, alpha1, Wd1, fbcp);
    conv1x1_tc<128><<<dim3(256, 1, NIMG), 256>>>(Wd1, bd1, x, x, alpha1, alpha1, fdp, 256);
    attn_s1<<<512, 256, 214272>>>(x, fbcp, fdp, alpha1, y1p);

    // ---- Stage 2 (z==8 slice of conv_fbc packs Wd2 -> g_wbf) -------------
    conv_fbc_tc<<<dim3(128, 1, 9), 256, FBC_SMEM>>>(
        Wb2, bb2, Wc2, bc2, x, y1p, alpha1, alpha2, Wd2, fbcp);
    attn_zhat<<<2048, 256, ZA_TOT * 4>>>(x, y1p, fbcp, alpha1, alpha2, (__nv_bfloat16*)fdp);
    conv_fe_bf<<<dim3(256, 1, NIMG), 256, FE_SMEM>>>(bd2, (const __nv_bfloat16*)fdp,
                                                     x, y1p, alpha1, alpha2, out);
}

// round 15
// speedup vs baseline: 1.0615x; 1.0346x over previous
#include <cuda_runtime.h>
#include <cuda_bf16.h>

#define NIMG 8
#define CIN  256
#define HW   16384      // 128*128
#define C8   32

// ---------------------------------------------------------------------------
// Scratch
// ---------------------------------------------------------------------------
__device__ float    g_y1 [NIMG * CIN * HW];
__device__ float    g_fd [NIMG * CIN * HW];   // stage-1 fd / stage-2 zhat (bf16 view)
__device__ float    g_fbc[NIMG * 64  * HW];
__device__ unsigned g_wbf[CIN * 128];         // Wd2 as bf16 pairs [o][k/2]

// ---------------------------------------------------------------------------
// Helpers
// ---------------------------------------------------------------------------
__device__ __forceinline__ unsigned f2tf(float f) {
    unsigned u; asm("cvt.rna.tf32.f32 %0, %1;" : "=r"(u) : "f"(f)); return u;
}
__device__ __forceinline__ void mma_tf32(float* c, const unsigned* a, unsigned b0, unsigned b1) {
    asm volatile("mma.sync.aligned.m16n8k8.row.col.f32.tf32.tf32.f32 "
                 "{%0,%1,%2,%3}, {%4,%5,%6,%7}, {%8,%9}, {%0,%1,%2,%3};"
                 : "+f"(c[0]), "+f"(c[1]), "+f"(c[2]), "+f"(c[3])
                 : "r"(a[0]), "r"(a[1]), "r"(a[2]), "r"(a[3]), "r"(b0), "r"(b1));
}
__device__ __forceinline__ void mma_bf16(float* c, const unsigned* a, unsigned b0, unsigned b1) {
    asm volatile("mma.sync.aligned.m16n8k16.row.col.f32.bf16.bf16.f32 "
                 "{%0,%1,%2,%3}, {%4,%5,%6,%7}, {%8,%9}, {%0,%1,%2,%3};"
                 : "+f"(c[0]), "+f"(c[1]), "+f"(c[2]), "+f"(c[3])
                 : "r"(a[0]), "r"(a[1]), "r"(a[2]), "r"(a[3]), "r"(b0), "r"(b1));
}
__device__ __forceinline__ unsigned pkbf(float lo, float hi) {
    __nv_bfloat162 h = __floats2bfloat162_rn(lo, hi);
    return *(unsigned*)&h;
}
__device__ __forceinline__ void cp16(unsigned dst, const void* src) {
    asm volatile("cp.async.cg.shared.global [%0], [%1], 16;" :: "r"(dst), "l"(src));
}
__device__ __forceinline__ void cp_commit() { asm volatile("cp.async.commit_group;"); }
__device__ __forceinline__ void cp_wait0()  { asm volatile("cp.async.wait_group 0;"); }

__device__ __forceinline__ unsigned smem_u32(const void* p) {
    unsigned a;
    asm("{ .reg .u64 t; cvta.to.shared.u64 t, %1; cvt.u32.u64 %0, t; }" : "=r"(a) : "l"(p));
    return a;
}

// ===========================================================================
// conv_fbc_tc: fbc = [Wb;Wc].in + [bb;bc]   (M=64, tf32, cp.async both ops)
// z==8 blocks pack Wfe -> g_wbf (bf16 pairs).
// Dynamic SMEM: Ws[2][64][36] | Xs[2][32][136]  = 53248 B
// ===========================================================================
#define FBC_SMEM ((2 * 64 * 36 + 2 * 32 * 136) * 4)

__device__ __forceinline__ void fbc_body(
    const float* __restrict__ Wb, const float* __restrict__ bb,
    const float* __restrict__ Wc, const float* __restrict__ bc,
    const float* __restrict__ in, float* __restrict__ out,
    int b, int p0, float* smf)
{
    float* Wbuf = smf;
    float* Xbuf = smf + 2 * 64 * 36;
    const unsigned wba = smem_u32(Wbuf);
    const unsigned xba = smem_u32(Xbuf);

    const int t = threadIdx.x, lane = t & 31, w = t >> 5;
    const int wm = w >> 2, wn = w & 3;
    const int g4 = lane >> 2, tg = lane & 3;

    float acc[2][4][4] = {};
    const float* inb = in + (size_t)b * CIN * HW + p0;

    auto issue = [&](int k0, int buf) {
        unsigned wd = wba + (unsigned)(buf * 64 * 36) * 4u;
        #pragma unroll
        for (int i = 0; i < 2; i++) {
            int fi = i * 256 + t, o = fi >> 3, k4 = (fi & 7) * 4;
            const float* src = (o < 32) ? &Wb[o * 256 + k0 + k4]
                                        : &Wc[(o - 32) * 256 + k0 + k4];
            cp16(wd + (unsigned)(o * 36 + k4) * 4u, src);
        }
        unsigned xd = xba + (unsigned)(buf * 32 * 136) * 4u;
        #pragma unroll
        for (int i = 0; i < 4; i++) {
            int fi = i * 256 + t, k = fi >> 5, seg = fi & 31;
            cp16(xd + (unsigned)(k * 136 + seg * 4) * 4u,
                 inb + (size_t)(k0 + k) * HW + seg * 4);
        }
        cp_commit();
    };

    issue(0, 0);
    cp_wait0(); __syncthreads();

    for (int c = 0; c < 8; c++) {
        if (c < 7) issue((c + 1) * 32, (c + 1) & 1);
        const float* Wd = Wbuf + (c & 1) * 64 * 36;
        const float* Xd = Xbuf + (c & 1) * 32 * 136;
        #pragma unroll
        for (int ks = 0; ks < 4; ks++) {
            unsigned a[2][4];
            int col = ks * 8 + tg;
            #pragma unroll
            for (int mt = 0; mt < 2; mt++) {
                int r = wm * 32 + mt * 16 + g4;
                a[mt][0] = __float_as_uint(Wd[r * 36 + col]);
                a[mt][1] = __float_as_uint(Wd[(r + 8) * 36 + col]);
                a[mt][2] = __float_as_uint(Wd[r * 36 + col + 4]);
                a[mt][3] = __float_as_uint(Wd[(r + 8) * 36 + col + 4]);
            }
            #pragma unroll
            for (int nt = 0; nt < 4; nt++) {
                int p = wn * 32 + nt * 8 + g4;
                unsigned b0 = __float_as_uint(Xd[(ks * 8 + tg) * 136 + p]);
                unsigned b1 = __float_as_uint(Xd[(ks * 8 + 4 + tg) * 136 + p]);
                mma_tf32(acc[0][nt], a[0], b0, b1);
                mma_tf32(acc[1][nt], a[1], b0, b1);
            }
        }
        if (c < 7) { cp_wait0(); __syncthreads(); }
    }

    #pragma unroll
    for (int mt = 0; mt < 2; mt++) {
        int o0 = wm * 32 + mt * 16 + g4, o1 = o0 + 8;
        float bs0 = (o0 < 32) ? bb[o0] : bc[o0 - 32];
        float bs1 = (o1 < 32) ? bb[o1] : bc[o1 - 32];
        #pragma unroll
        for (int nt = 0; nt < 4; nt++) {
            int p = p0 + wn * 32 + nt * 8 + tg * 2;
            *(float2*)&out[((size_t)b * 64 + o0) * HW + p] =
                make_float2(acc[mt][nt][0] + bs0, acc[mt][nt][1] + bs0);
            *(float2*)&out[((size_t)b * 64 + o1) * HW + p] =
                make_float2(acc[mt][nt][2] + bs1, acc[mt][nt][3] + bs1);
        }
    }
}

__global__ void __launch_bounds__(256, 3) conv_fbc_tc(
    const float* __restrict__ Wb, const float* __restrict__ bb,
    const float* __restrict__ Wc, const float* __restrict__ bc,
    const float* __restrict__ inA, const float* __restrict__ inB,
    const float* __restrict__ sel, const float* __restrict__ guard,
    const float* __restrict__ Wfe,
    float* __restrict__ out)
{
    if (guard[0] == 0.0f) return;
    if (blockIdx.z == 8) {                 // folded wcvt
        int idx = blockIdx.x * 256 + threadIdx.x;
        int o = idx >> 7, kp = idx & 127;
        g_wbf[idx] = pkbf(Wfe[o * 256 + kp * 2], Wfe[o * 256 + kp * 2 + 1]);
        return;
    }
    extern __shared__ float smf[];
    const float* in = (sel[0] == 0.0f) ? inA : inB;
    fbc_body(Wb, bb, Wc, bc, in, out, blockIdx.z, blockIdx.x * 128, smf);
}

// ===========================================================================
// stage1_convs: merged stage-1 fbc conv (x<128) + fd conv (x>=128).
// General path only; skips entirely when alpha1 == 0.
// ===========================================================================
__global__ void __launch_bounds__(256, 3) stage1_convs(
    const float* __restrict__ Wb, const float* __restrict__ bb,
    const float* __restrict__ Wc, const float* __restrict__ bc,
    const float* __restrict__ Wd, const float* __restrict__ bd,
    const float* __restrict__ x, const float* __restrict__ alpha1,
    float* __restrict__ fbc_out, float* __restrict__ fd_out)
{
    if (alpha1[0] == 0.0f) return;
    extern __shared__ float smf[];
    const int b = blockIdx.z;

    if (blockIdx.x < 128) {                // fbc path
        fbc_body(Wb, bb, Wc, bc, x, fbc_out, b, blockIdx.x * 128, smf);
        return;
    }

    // fd conv path: M=256 in two 128-row tiles, 128-pixel tiles
    const int idx = blockIdx.x - 128;      // 0..255
    const int m0 = (idx & 1) * 128, p0 = (idx >> 1) * 128;

    float* Ws = smf;                       // [128][36]
    float* Xs = smf + 128 * 36;            // [32][136]

    const int t = threadIdx.x, lane = t & 31, w = t >> 5;
    const int wm = w >> 1, wn = w & 1;
    const int g4 = lane >> 2, tg = lane & 3;

    float acc[2][8][4];
    #pragma unroll
    for (int i = 0; i < 2; i++)
        #pragma unroll
        for (int j = 0; j < 8; j++)
            #pragma unroll
            for (int q = 0; q < 4; q++) acc[i][j][q] = 0.f;

    const float* inb = x + (size_t)b * CIN * HW + p0;
    float4 wreg[4], xreg[4];

    auto loadW = [&](int k0) {
        #pragma unroll
        for (int i = 0; i < 4; i++) {
            int fi = i * 256 + t, o = fi >> 3, k4 = (fi & 7) * 4;
            wreg[i] = *(const float4*)&Wd[(m0 + o) * CIN + k0 + k4];
        }
    };
    auto loadX = [&](int k0) {
        #pragma unroll
        for (int i = 0; i < 4; i++) {
            int fi = i * 256 + t, k = fi >> 5, p4 = (fi & 31) * 4;
            xreg[i] = *(const float4*)&inb[(size_t)(k0 + k) * HW + p4];
        }
    };
    auto storeW = [&]() {
        #pragma unroll
        for (int i = 0; i < 4; i++) {
            int fi = i * 256 + t, o = fi >> 3, k4 = (fi & 7) * 4;
            float4 v = wreg[i];
            Ws[o * 36 + k4 + 0] = __uint_as_float(f2tf(v.x));
            Ws[o * 36 + k4 + 1] = __uint_as_float(f2tf(v.y));
            Ws[o * 36 + k4 + 2] = __uint_as_float(f2tf(v.z));
            Ws[o * 36 + k4 + 3] = __uint_as_float(f2tf(v.w));
        }
    };
    auto storeX = [&]() {
        #pragma unroll
        for (int i = 0; i < 4; i++) {
            int fi = i * 256 + t, k = fi >> 5, p4 = (fi & 31) * 4;
            float4 v = xreg[i];
            Xs[k * 136 + p4 + 0] = __uint_as_float(f2tf(v.x));
            Xs[k * 136 + p4 + 1] = __uint_as_float(f2tf(v.y));
            Xs[k * 136 + p4 + 2] = __uint_as_float(f2tf(v.z));
            Xs[k * 136 + p4 + 3] = __uint_as_float(f2tf(v.w));
        }
    };

    loadW(0); loadX(0);
    storeW(); storeX();
    __syncthreads();

    for (int c = 0; c < 8; c++) {
        if (c < 7) { loadW((c + 1) * 32); loadX((c + 1) * 32); }
        #pragma unroll
        for (int ks = 0; ks < 4; ks++) {
            unsigned a[2][4];
            int col = ks * 8 + tg;
            #pragma unroll
            for (int mt = 0; mt < 2; mt++) {
                int r = wm * 32 + mt * 16 + g4;
                a[mt][0] = __float_as_uint(Ws[r * 36 + col]);
                a[mt][1] = __float_as_uint(Ws[(r + 8) * 36 + col]);
                a[mt][2] = __float_as_uint(Ws[r * 36 + col + 4]);
                a[mt][3] = __float_as_uint(Ws[(r + 8) * 36 + col + 4]);
            }
            #pragma unroll
            for (int nt = 0; nt < 8; nt++) {
                int p = wn * 64 + nt * 8 + g4;
                unsigned b0 = __float_as_uint(Xs[(ks * 8 + tg) * 136 + p]);
                unsigned b1 = __float_as_uint(Xs[(ks * 8 + 4 + tg) * 136 + p]);
                mma_tf32(acc[0][nt], a[0], b0, b1);
                mma_tf32(acc[1][nt], a[1], b0, b1);
            }
        }
        __syncthreads();
        if (c < 7) { storeW(); storeX(); __syncthreads(); }
    }

    #pragma unroll
    for (int mt = 0; mt < 2; mt++) {
        int o0 = m0 + wm * 32 + mt * 16 + g4;
        float bs0 = bd[o0], bs1 = bd[o0 + 8];
        #pragma unroll
        for (int nt = 0; nt < 8; nt++) {
            int p = p0 + wn * 64 + nt * 8 + tg * 2;
            float2 v0 = make_float2(acc[mt][nt][0] + bs0, acc[mt][nt][1] + bs0);
            float2 v1 = make_float2(acc[mt][nt][2] + bs1, acc[mt][nt][3] + bs1);
            *(float2*)&fd_out[((size_t)b * CIN + o0) * HW + p]     = v0;
            *(float2*)&fd_out[((size_t)b * CIN + o0 + 8) * HW + p] = v1;
        }
    }
}

// ===========================================================================
// attn_zhat (occ 3): fbc via cp.async (overlapped with y convert);
// logits(fp32)+softmax, zhat = A.y^T bf16 -> [n][pix][256c]
// ===========================================================================
#define ZA_YS  0
#define ZA_FB  (256 * 36)
#define ZA_AS  (ZA_FB + 64 * 68)
#define ZA_TOT (ZA_AS + 64 * 36)

__global__ void __launch_bounds__(256, 3) attn_zhat(
    const float* __restrict__ x, const float* __restrict__ y1,
    const float* __restrict__ fbc,
    const float* __restrict__ alpha1_p, const float* __restrict__ alpha2_p,
    __nv_bfloat16* __restrict__ zout)
{
    if (alpha2_p[0] == 0.0f) return;
    const float* y = (alpha1_p[0] == 0.0f) ? x : y1;

    extern __shared__ unsigned smu[];
    unsigned* ysp = smu + ZA_YS;
    float*    fb  = (float*)(smu + ZA_FB);
    unsigned* Asp = smu + ZA_AS;
    unsigned* zh  = smu + ZA_YS;

    const int beta = blockIdx.x;
    const int n  = beta >> 8;
    const int qh = (beta >> 4) & 15, qw = beta & 15;
    const int base = (qh * 8) * 128 + qw * 8;
    const int t = threadIdx.x, lane = t & 31, w = t >> 5;
    const int g4 = lane >> 2, tg = lane & 3;

    {   // fbc tile via cp.async; y tile sync-load + bf16 pack (overlapped)
        const unsigned fba = smem_u32(fb);
        const float* fbb = fbc + (size_t)n * 64 * HW + base;
        #pragma unroll
        for (int i = 0; i < 4; i++) {
            int fi = i * 256 + t;
            int r = fi >> 4, jr = (fi >> 1) & 7, jc = (fi & 1) * 4;
            cp16(fba + (unsigned)(r * 68 + jr * 8 + jc) * 4u,
                 &fbb[(size_t)r * HW + jr * 128 + jc]);
        }
        cp_commit();

        const float* yb = y + (size_t)n * CIN * HW + base;
        #pragma unroll
        for (int i = 0; i < 16; i++) {
            int fi = i * 256 + t;
            int c = fi >> 4, jr = (fi >> 1) & 7, jc = (fi & 1) * 4;
            float4 v = *(const float4*)&yb[(size_t)c * HW + jr * 128 + jc];
            int j0 = jr * 4 + (jc >> 1);
            uint2 pk = make_uint2(pkbf(v.x, v.y), pkbf(v.z, v.w));
            *(uint2*)&ysp[c * 36 + j0] = pk;
        }
        cp_wait0();
    }
    __syncthreads();

    {   // logits + softmax (fp32)
        const int l = t >> 2, mq = t & 3;
        float fbl[32];
        #pragma unroll
        for (int k = 0; k < 32; k++) fbl[k] = fb[k * 68 + l];
        float s[16];
        #pragma unroll
        for (int mm = 0; mm < 16; mm++) {
            int m = mq * 16 + mm;
            float v = 0.f;
            #pragma unroll
            for (int k = 0; k < 32; k++) v += fbl[k] * fb[(32 + k) * 68 + m];
            s[mm] = v;
        }
        float mx = -1e30f;
        #pragma unroll
        for (int i = 0; i < 16; i++) mx = fmaxf(mx, s[i]);
        mx = fmaxf(mx, __shfl_xor_sync(0xffffffff, mx, 1));
        mx = fmaxf(mx, __shfl_xor_sync(0xffffffff, mx, 2));
        float sum = 0.f;
        #pragma unroll
        for (int i = 0; i < 16; i++) { s[i] = __expf(s[i] - mx); sum += s[i]; }
        sum += __shfl_xor_sync(0xffffffff, sum, 1);
        sum += __shfl_xor_sync(0xffffffff, sum, 2);
        float inv = 1.0f / sum;
        #pragma unroll
        for (int q = 0; q < 8; q++)
            Asp[l * 36 + mq * 8 + q] = pkbf(s[2 * q] * inv, s[2 * q + 1] * inv);
    }
    __syncthreads();

    {   // zhat = A . y^T  (M64 l, N256 c, K64 m), bf16
        const int wm = w >> 2, wc = w & 3;
        const int m0 = wm * 32, c0w = wc * 64;
        float acc[2][8][4];
        #pragma unroll
        for (int i = 0; i < 2; i++)
            #pragma unroll
            for (int j = 0; j < 8; j++)
                #pragma unroll
                for (int q = 0; q < 4; q++) acc[i][j][q] = 0.f;
        #pragma unroll
        for (int ks = 0; ks < 4; ks++) {
            unsigned a[2][4];
            int col = ks * 8 + tg;
            #pragma unroll
            for (int mt = 0; mt < 2; mt++) {
                int r = m0 + mt * 16 + g4;
                a[mt][0] = Asp[r * 36 + col];
                a[mt][1] = Asp[(r + 8) * 36 + col];
                a[mt][2] = Asp[r * 36 + col + 4];
                a[mt][3] = Asp[(r + 8) * 36 + col + 4];
            }
            #pragma unroll
            for (int nt = 0; nt < 8; nt++) {
                int c = c0w + nt * 8 + g4;
                unsigned b0 = ysp[c * 36 + col];
                unsigned b1 = ysp[c * 36 + col + 4];
                mma_bf16(acc[0][nt], a[0], b0, b1);
                mma_bf16(acc[1][nt], a[1], b0, b1);
            }
        }
        __syncthreads();                       // ysp reads done -> zh alias safe
        #pragma unroll
        for (int mt = 0; mt < 2; mt++) {
            int l0 = m0 + mt * 16 + g4;
            #pragma unroll
            for (int nt = 0; nt < 8; nt++) {
                int cp = wc * 32 + nt * 4 + tg;
                zh[l0 * 132 + cp]       = pkbf(acc[mt][nt][0], acc[mt][nt][1]);
                zh[(l0 + 8) * 132 + cp] = pkbf(acc[mt][nt][2], acc[mt][nt][3]);
            }
        }
    }
    __syncthreads();

    {   // coalesced global write: [pix][c] bf16
        unsigned* zb = (unsigned*)zout + (size_t)n * HW * 128;
        #pragma unroll
        for (int i = 0; i < 32; i++) {
            int fi = i * 256 + t;
            int l = fi >> 7, cq = fi & 127;
            int pix = base + (l >> 3) * 128 + (l & 7);
            zb[(size_t)pix * 128 + cq] = zh[l * 132 + cq];
        }
    }
}

// ===========================================================================
// conv_fe_bf (R14-best): out = alpha*(Wd.zhat + bd) + y, bf16 mma.
// Full X panel resident (cp.async), W bf16 pre-packed, cp.async double-buffered.
// Dynamic SMEM: Wsp[2][128][20] | Xs[128][132]  = 88064 B, occ 2.
// ===========================================================================
#define FE_SMEM ((2 * 128 * 20 + 128 * 132) * 4)

__global__ void __launch_bounds__(256, 2) conv_fe_bf(
    const float* __restrict__ bias,
    const __nv_bfloat16* __restrict__ zin,
    const float* __restrict__ x, const float* __restrict__ y1,
    const float* __restrict__ alpha1_p, const float* __restrict__ alpha2_p,
    float* __restrict__ out)
{
    const float alpha = alpha2_p[0];
    const float* y = (alpha1_p[0] == 0.0f) ? x : y1;

    const int b  = blockIdx.z;
    const int mi = blockIdx.x & 1;
    const int pi = blockIdx.x >> 1;
    const int m0 = mi * 128, p0 = pi * 128;
    const int t = threadIdx.x, lane = t & 31, w = t >> 5;

    if (alpha == 0.0f) {                   // identity: copy this tile
        const float* yt = y + ((size_t)b * CIN + m0) * HW + p0;
        float* ot = out + ((size_t)b * CIN + m0) * HW + p0;
        #pragma unroll
        for (int i = 0; i < 16; i++) {
            int fi = i * 256 + t;
            int o = fi >> 5, q = (fi & 31) * 4;
            *(float4*)&ot[(size_t)o * HW + q] = *(const float4*)&yt[(size_t)o * HW + q];
        }
        return;
    }

    extern __shared__ unsigned smw[];
    unsigned* Wsp = smw;                   // [2][128][20]
    unsigned* Xs  = smw + 2 * 128 * 20;    // [128][132]
    const unsigned wba = smem_u32(Wsp);
    const unsigned xba = smem_u32(Xs);

    const int wm = w >> 1, wn = w & 1;
    const int g4 = lane >> 2, tg = lane & 3;

    float acc[2][8][4];
    #pragma unroll
    for (int i = 0; i < 2; i++)
        #pragma unroll
        for (int j = 0; j < 8; j++)
            #pragma unroll
            for (int q = 0; q < 4; q++) acc[i][j][q] = 0.f;

    const unsigned* zb = (const unsigned*)zin + (size_t)b * HW * 128 + (size_t)p0 * 128;

    auto issueX = [&]() {                  // full 128x128-u32 panel
        #pragma unroll
        for (int i = 0; i < 16; i++) {
            int fi = i * 256 + t, p = fi >> 5, seg = fi & 31;
            cp16(xba + (unsigned)(p * 132 + seg * 4) * 4u, zb + (size_t)p * 128 + seg * 4);
        }
    };
    auto issueW = [&](int c, int buf) {    // W chunk: 128 rows x 16 u32
        unsigned dst = wba + (unsigned)(buf * 128 * 20) * 4u;
        #pragma unroll
        for (int i = 0; i < 2; i++) {
            int fi = i * 256 + t, o = fi >> 2, seg = fi & 3;
            cp16(dst + (unsigned)(o * 20 + seg * 4) * 4u,
                 g_wbf + (size_t)(m0 + o) * 128 + c * 16 + seg * 4);
        }
        cp_commit();
    };

    issueX();
    issueW(0, 0);                          // group contains X + W0
    cp_wait0(); __syncthreads();

    for (int c = 0; c < 8; c++) {
        if (c < 7) issueW(c + 1, (c + 1) & 1);
        const unsigned* Wd = Wsp + (c & 1) * 128 * 20;
        #pragma unroll
        for (int ks = 0; ks < 2; ks++) {
            unsigned a[2][4];
            int col = ks * 8 + tg;
            #pragma unroll
            for (int mt = 0; mt < 2; mt++) {
                int r = wm * 32 + mt * 16 + g4;
                a[mt][0] = Wd[r * 20 + col];
                a[mt][1] = Wd[(r + 8) * 20 + col];
                a[mt][2] = Wd[r * 20 + col + 4];
                a[mt][3] = Wd[(r + 8) * 20 + col + 4];
            }
            #pragma unroll
            for (int nt = 0; nt < 8; nt++) {
                int p = wn * 64 + nt * 8 + g4;
                unsigned b0 = Xs[p * 132 + c * 16 + col];
                unsigned b1 = Xs[p * 132 + c * 16 + col + 4];
                mma_bf16(acc[0][nt], a[0], b0, b1);
                mma_bf16(acc[1][nt], a[1], b0, b1);
            }
        }
        if (c < 7) { cp_wait0(); __syncthreads(); }
    }

    #pragma unroll
    for (int mt = 0; mt < 2; mt++) {
        int o0 = m0 + wm * 32 + mt * 16 + g4;
        float bs0 = bias[o0], bs1 = bias[o0 + 8];
        const float* yr0 = y + ((size_t)b * CIN + o0) * HW + p0;
        const float* yr1 = y + ((size_t)b * CIN + o0 + 8) * HW + p0;
        float* ob0 = out + ((size_t)b * CIN + o0) * HW + p0;
        float* ob1 = out + ((size_t)b * CIN + o0 + 8) * HW + p0;
        #pragma unroll
        for (int nt = 0; nt < 8; nt++) {
            int p = wn * 64 + nt * 8 + tg * 2;
            float2 yv0 = *(const float2*)&yr0[p];
            float2 yv1 = *(const float2*)&yr1[p];
            float2 v0 = make_float2(alpha * (acc[mt][nt][0] + bs0) + yv0.x,
                                    alpha * (acc[mt][nt][1] + bs0) + yv0.y);
            float2 v1 = make_float2(alpha * (acc[mt][nt][2] + bs1) + yv1.x,
                                    alpha * (acc[mt][nt][3] + bs1) + yv1.y);
            *(float2*)&ob0[p] = v0;
            *(float2*)&ob1[p] = v1;
        }
    }
}

// ---------------------------------------------------------------------------
// Stage-1 attention (general path; skipped when alpha1==0)
// ---------------------------------------------------------------------------
__global__ void __launch_bounds__(256) attn_s1(
    const float* __restrict__ x, const float* __restrict__ fbc,
    const float* __restrict__ fd, const float* __restrict__ alpha_p,
    float* __restrict__ y1)
{
    const float alpha = alpha_p[0];
    if (alpha == 0.0f) return;
    extern __shared__ float sm1f[];
    float* fbc_s = sm1f;
    float* fdc_s = fbc_s + 64 * 256;
    __nv_bfloat16* A_s = (__nv_bfloat16*)(fdc_s + 16 * 260);

    const int beta = blockIdx.x;
    const int n  = beta >> 6;
    const int ph = (beta >> 3) & 7, pw = beta & 7;
    const int t = threadIdx.x;

    for (int idx = t; idx < 64 * 256; idx += 256) {
        int r = idx >> 8, j = idx & 255;
        fbc_s[r * 256 + j] = fbc[(n * 64 + r) * HW + ((j >> 4) * 8 + ph) * 128 + (j & 15) * 8 + pw];
    }
    __syncthreads();

    float fbl[32];
    #pragma unroll
    for (int k = 0; k < 32; k++) fbl[k] = fbc_s[k * 256 + t];

    float mx = -1e30f, den = 0.f;
    for (int m = 0; m < 256; m++) {
        float s = 0.f;
        #pragma unroll
        for (int k = 0; k < 32; k++) s += fbl[k] * fbc_s[(32 + k) * 256 + m];
        if (s > mx) { den *= __expf(mx - s); mx = s; }
        den += __expf(s - mx);
    }
    float inv = 1.0f / den;
    for (int m = 0; m < 256; m++) {
        float s = 0.f;
        #pragma unroll
        for (int k = 0; k < 32; k++) s += fbl[k] * fbc_s[(32 + k) * 256 + m];
        A_s[t * 258 + m] = __float2bfloat16(__expf(s - mx) * inv);
    }
    __syncthreads();

    for (int cc = 0; cc < 16; cc++) {
        for (int idx = t; idx < 16 * 256; idx += 256) {
            int c = idx >> 8, j = idx & 255;
            fdc_s[c * 260 + j] = fd[(n * CIN + cc * 16 + c) * HW +
                                    ((j >> 4) * 8 + ph) * 128 + (j & 15) * 8 + pw];
        }
        __syncthreads();
        float acc[16] = {};
        for (int m = 0; m < 256; m++) {
            float a = __bfloat162float(A_s[t * 258 + m]);
            #pragma unroll
            for (int c = 0; c < 16; c++) acc[c] += a * fdc_s[c * 260 + m];
        }
        const int pix = ((t >> 4) * 8 + ph) * 128 + (t & 15) * 8 + pw;
        #pragma unroll
        for (int c = 0; c < 16; c++) {
            int off = (n * CIN + cc * 16 + c) * HW + pix;
            y1[off] = alpha * acc[c] + x[off];
        }
        __syncthreads();
    }
}

// ---------------------------------------------------------------------------
// Host launcher — 5 launches total
// ---------------------------------------------------------------------------
extern "C" void kernel_launch(void* const* d_in, const int* in_sizes, int n_in,
                              void* d_out, int out_size)
{
    const float* x      = (const float*)d_in[0];
    const float* Wb1    = (const float*)d_in[1];
    const float* bb1    = (const float*)d_in[2];
    const float* Wc1    = (const float*)d_in[3];
    const float* bc1    = (const float*)d_in[4];
    const float* Wd1    = (const float*)d_in[5];
    const float* bd1    = (const float*)d_in[6];
    const float* alpha1 = (const float*)d_in[7];
    const float* Wb2    = (const float*)d_in[8];
    const float* bb2    = (const float*)d_in[9];
    const float* Wc2    = (const float*)d_in[10];
    const float* bc2    = (const float*)d_in[11];
    const float* Wd2    = (const float*)d_in[12];
    const float* bd2    = (const float*)d_in[13];
    const float* alpha2 = (const float*)d_in[14];
    float* out = (float*)d_out;

    cudaFuncSetAttribute(attn_s1, cudaFuncAttributeMaxDynamicSharedMemorySize, 214272);
    cudaFuncSetAttribute(attn_zhat, cudaFuncAttributeMaxDynamicSharedMemorySize, ZA_TOT * 4);
    cudaFuncSetAttribute(conv_fbc_tc, cudaFuncAttributeMaxDynamicSharedMemorySize, FBC_SMEM);
    cudaFuncSetAttribute(stage1_convs, cudaFuncAttributeMaxDynamicSharedMemorySize, FBC_SMEM);
    cudaFuncSetAttribute(conv_fe_bf, cudaFuncAttributeMaxDynamicSharedMemorySize, FE_SMEM);

    float *y1p, *fdp, *fbcp;
    cudaGetSymbolAddress((void**)&y1p,  g_y1);
    cudaGetSymbolAddress((void**)&fdp,  g_fd);
    cudaGetSymbolAddress((void**)&fbcp, g_fbc);

    // ---- Stage 1 (general path; both kernels self-skip when alpha1==0) --
    stage1_convs<<<dim3(384, 1, NIMG), 256, FBC_SMEM>>>(
        Wb1, bb1, Wc1, bc1, Wd1, bd1, x, alpha1, fbcp, fdp);
    attn_s1<<<512, 256, 214272>>>(x, fbcp, fdp, alpha1, y1p);

    // ---- Stage 2 (z==8 slice of conv_fbc packs Wd2 -> g_wbf) -------------
    conv_fbc_tc<<<dim3(128, 1, 9), 256, FBC_SMEM>>>(
        Wb2, bb2, Wc2, bc2, x, y1p, alpha1, alpha2, Wd2, fbcp);
    attn_zhat<<<2048, 256, ZA_TOT * 4>>>(x, y1p, fbcp, alpha1, alpha2, (__nv_bfloat16*)fdp);
    conv_fe_bf<<<dim3(256, 1, NIMG), 256, FE_SMEM>>>(bd2, (const __nv_bfloat16*)fdp,
                                                     x, y1p, alpha1, alpha2, out);
}

// round 16
// speedup vs baseline: 1.2659x; 1.1925x over previous
#include <cuda_runtime.h>
#include <cuda_bf16.h>

#define NIMG 8
#define CIN  256
#define HW   16384      // 128*128
#define C8   32

// ---------------------------------------------------------------------------
// Scratch
// ---------------------------------------------------------------------------
__device__ float    g_y1 [NIMG * CIN * HW];
__device__ float    g_fd [NIMG * CIN * HW];   // stage-1 fd / stage-2 zhat (bf16 view)
__device__ float    g_fbc[NIMG * 64  * HW];
__device__ unsigned g_wbf[CIN * 128];         // Wd2 as bf16 pairs [o][k/2]

// ---------------------------------------------------------------------------
// Helpers
// ---------------------------------------------------------------------------
__device__ __forceinline__ unsigned f2tf(float f) {
    unsigned u; asm("cvt.rna.tf32.f32 %0, %1;" : "=r"(u) : "f"(f)); return u;
}
__device__ __forceinline__ void mma_tf32(float* c, const unsigned* a, unsigned b0, unsigned b1) {
    asm volatile("mma.sync.aligned.m16n8k8.row.col.f32.tf32.tf32.f32 "
                 "{%0,%1,%2,%3}, {%4,%5,%6,%7}, {%8,%9}, {%0,%1,%2,%3};"
                 : "+f"(c[0]), "+f"(c[1]), "+f"(c[2]), "+f"(c[3])
                 : "r"(a[0]), "r"(a[1]), "r"(a[2]), "r"(a[3]), "r"(b0), "r"(b1));
}
__device__ __forceinline__ void mma_bf16(float* c, const unsigned* a, unsigned b0, unsigned b1) {
    asm volatile("mma.sync.aligned.m16n8k16.row.col.f32.bf16.bf16.f32 "
                 "{%0,%1,%2,%3}, {%4,%5,%6,%7}, {%8,%9}, {%0,%1,%2,%3};"
                 : "+f"(c[0]), "+f"(c[1]), "+f"(c[2]), "+f"(c[3])
                 : "r"(a[0]), "r"(a[1]), "r"(a[2]), "r"(a[3]), "r"(b0), "r"(b1));
}
__device__ __forceinline__ unsigned pkbf(float lo, float hi) {
    __nv_bfloat162 h = __floats2bfloat162_rn(lo, hi);
    return *(unsigned*)&h;
}
__device__ __forceinline__ void cp16(unsigned dst, const void* src) {
    asm volatile("cp.async.cg.shared.global [%0], [%1], 16;" :: "r"(dst), "l"(src));
}
__device__ __forceinline__ void cp_commit() { asm volatile("cp.async.commit_group;"); }
__device__ __forceinline__ void cp_wait0()  { asm volatile("cp.async.wait_group 0;"); }

__device__ __forceinline__ unsigned smem_u32(const void* p) {
    unsigned a;
    asm("{ .reg .u64 t; cvta.to.shared.u64 t, %1; cvt.u32.u64 %0, t; }" : "=r"(a) : "l"(p));
    return a;
}

// ===========================================================================
// conv_fbc_tc: fbc = [Wb;Wc].in + [bb;bc]   (M=64, tf32, cp.async both ops)
// z==8 blocks pack Wfe -> g_wbf (bf16 pairs).
// Dynamic SMEM: Ws[2][64][36] | Xs[2][32][136]  = 53248 B
// ===========================================================================
#define FBC_SMEM ((2 * 64 * 36 + 2 * 32 * 136) * 4)

__device__ __forceinline__ void fbc_body(
    const float* __restrict__ Wb, const float* __restrict__ bb,
    const float* __restrict__ Wc, const float* __restrict__ bc,
    const float* __restrict__ in, float* __restrict__ out,
    int b, int p0, float* smf)
{
    float* Wbuf = smf;
    float* Xbuf = smf + 2 * 64 * 36;
    const unsigned wba = smem_u32(Wbuf);
    const unsigned xba = smem_u32(Xbuf);

    const int t = threadIdx.x, lane = t & 31, w = t >> 5;
    const int wm = w >> 2, wn = w & 3;
    const int g4 = lane >> 2, tg = lane & 3;

    float acc[2][4][4] = {};
    const float* inb = in + (size_t)b * CIN * HW + p0;

    auto issue = [&](int k0, int buf) {
        unsigned wd = wba + (unsigned)(buf * 64 * 36) * 4u;
        #pragma unroll
        for (int i = 0; i < 2; i++) {
            int fi = i * 256 + t, o = fi >> 3, k4 = (fi & 7) * 4;
            const float* src = (o < 32) ? &Wb[o * 256 + k0 + k4]
                                        : &Wc[(o - 32) * 256 + k0 + k4];
            cp16(wd + (unsigned)(o * 36 + k4) * 4u, src);
        }
        unsigned xd = xba + (unsigned)(buf * 32 * 136) * 4u;
        #pragma unroll
        for (int i = 0; i < 4; i++) {
            int fi = i * 256 + t, k = fi >> 5, seg = fi & 31;
            cp16(xd + (unsigned)(k * 136 + seg * 4) * 4u,
                 inb + (size_t)(k0 + k) * HW + seg * 4);
        }
        cp_commit();
    };

    issue(0, 0);
    cp_wait0(); __syncthreads();

    for (int c = 0; c < 8; c++) {
        if (c < 7) issue((c + 1) * 32, (c + 1) & 1);
        const float* Wd = Wbuf + (c & 1) * 64 * 36;
        const float* Xd = Xbuf + (c & 1) * 32 * 136;
        #pragma unroll
        for (int ks = 0; ks < 4; ks++) {
            unsigned a[2][4];
            int col = ks * 8 + tg;
            #pragma unroll
            for (int mt = 0; mt < 2; mt++) {
                int r = wm * 32 + mt * 16 + g4;
                a[mt][0] = __float_as_uint(Wd[r * 36 + col]);
                a[mt][1] = __float_as_uint(Wd[(r + 8) * 36 + col]);
                a[mt][2] = __float_as_uint(Wd[r * 36 + col + 4]);
                a[mt][3] = __float_as_uint(Wd[(r + 8) * 36 + col + 4]);
            }
            #pragma unroll
            for (int nt = 0; nt < 4; nt++) {
                int p = wn * 32 + nt * 8 + g4;
                unsigned b0 = __float_as_uint(Xd[(ks * 8 + tg) * 136 + p]);
                unsigned b1 = __float_as_uint(Xd[(ks * 8 + 4 + tg) * 136 + p]);
                mma_tf32(acc[0][nt], a[0], b0, b1);
                mma_tf32(acc[1][nt], a[1], b0, b1);
            }
        }
        if (c < 7) { cp_wait0(); __syncthreads(); }
    }

    #pragma unroll
    for (int mt = 0; mt < 2; mt++) {
        int o0 = wm * 32 + mt * 16 + g4, o1 = o0 + 8;
        float bs0 = (o0 < 32) ? bb[o0] : bc[o0 - 32];
        float bs1 = (o1 < 32) ? bb[o1] : bc[o1 - 32];
        #pragma unroll
        for (int nt = 0; nt < 4; nt++) {
            int p = p0 + wn * 32 + nt * 8 + tg * 2;
            *(float2*)&out[((size_t)b * 64 + o0) * HW + p] =
                make_float2(acc[mt][nt][0] + bs0, acc[mt][nt][1] + bs0);
            *(float2*)&out[((size_t)b * 64 + o1) * HW + p] =
                make_float2(acc[mt][nt][2] + bs1, acc[mt][nt][3] + bs1);
        }
    }
}

__global__ void __launch_bounds__(256, 3) conv_fbc_tc(
    const float* __restrict__ Wb, const float* __restrict__ bb,
    const float* __restrict__ Wc, const float* __restrict__ bc,
    const float* __restrict__ inA, const float* __restrict__ inB,
    const float* __restrict__ sel, const float* __restrict__ guard,
    const float* __restrict__ Wfe,
    float* __restrict__ out)
{
    if (guard[0] == 0.0f) return;
    if (blockIdx.z == 8) {                 // folded wcvt
        int idx = blockIdx.x * 256 + threadIdx.x;
        int o = idx >> 7, kp = idx & 127;
        g_wbf[idx] = pkbf(Wfe[o * 256 + kp * 2], Wfe[o * 256 + kp * 2 + 1]);
        return;
    }
    extern __shared__ float smf[];
    const float* in = (sel[0] == 0.0f) ? inA : inB;
    fbc_body(Wb, bb, Wc, bc, in, out, blockIdx.z, blockIdx.x * 128, smf);
}

// ===========================================================================
// stage1_convs: merged stage-1 fbc conv (x<128) + fd conv (x>=128).
// General path only; skips entirely when alpha1 == 0.
// ===========================================================================
__global__ void __launch_bounds__(256, 3) stage1_convs(
    const float* __restrict__ Wb, const float* __restrict__ bb,
    const float* __restrict__ Wc, const float* __restrict__ bc,
    const float* __restrict__ Wd, const float* __restrict__ bd,
    const float* __restrict__ x, const float* __restrict__ alpha1,
    float* __restrict__ fbc_out, float* __restrict__ fd_out)
{
    if (alpha1[0] == 0.0f) return;
    extern __shared__ float smf[];
    const int b = blockIdx.z;

    if (blockIdx.x < 128) {                // fbc path
        fbc_body(Wb, bb, Wc, bc, x, fbc_out, b, blockIdx.x * 128, smf);
        return;
    }

    // fd conv path: M=256 in two 128-row tiles, 128-pixel tiles
    const int idx = blockIdx.x - 128;      // 0..255
    const int m0 = (idx & 1) * 128, p0 = (idx >> 1) * 128;

    float* Ws = smf;                       // [128][36]
    float* Xs = smf + 128 * 36;            // [32][136]

    const int t = threadIdx.x, lane = t & 31, w = t >> 5;
    const int wm = w >> 1, wn = w & 1;
    const int g4 = lane >> 2, tg = lane & 3;

    float acc[2][8][4];
    #pragma unroll
    for (int i = 0; i < 2; i++)
        #pragma unroll
        for (int j = 0; j < 8; j++)
            #pragma unroll
            for (int q = 0; q < 4; q++) acc[i][j][q] = 0.f;

    const float* inb = x + (size_t)b * CIN * HW + p0;
    float4 wreg[4], xreg[4];

    auto loadW = [&](int k0) {
        #pragma unroll
        for (int i = 0; i < 4; i++) {
            int fi = i * 256 + t, o = fi >> 3, k4 = (fi & 7) * 4;
            wreg[i] = *(const float4*)&Wd[(m0 + o) * CIN + k0 + k4];
        }
    };
    auto loadX = [&](int k0) {
        #pragma unroll
        for (int i = 0; i < 4; i++) {
            int fi = i * 256 + t, k = fi >> 5, p4 = (fi & 31) * 4;
            xreg[i] = *(const float4*)&inb[(size_t)(k0 + k) * HW + p4];
        }
    };
    auto storeW = [&]() {
        #pragma unroll
        for (int i = 0; i < 4; i++) {
            int fi = i * 256 + t, o = fi >> 3, k4 = (fi & 7) * 4;
            float4 v = wreg[i];
            Ws[o * 36 + k4 + 0] = __uint_as_float(f2tf(v.x));
            Ws[o * 36 + k4 + 1] = __uint_as_float(f2tf(v.y));
            Ws[o * 36 + k4 + 2] = __uint_as_float(f2tf(v.z));
            Ws[o * 36 + k4 + 3] = __uint_as_float(f2tf(v.w));
        }
    };
    auto storeX = [&]() {
        #pragma unroll
        for (int i = 0; i < 4; i++) {
            int fi = i * 256 + t, k = fi >> 5, p4 = (fi & 31) * 4;
            float4 v = xreg[i];
            Xs[k * 136 + p4 + 0] = __uint_as_float(f2tf(v.x));
            Xs[k * 136 + p4 + 1] = __uint_as_float(f2tf(v.y));
            Xs[k * 136 + p4 + 2] = __uint_as_float(f2tf(v.z));
            Xs[k * 136 + p4 + 3] = __uint_as_float(f2tf(v.w));
        }
    };

    loadW(0); loadX(0);
    storeW(); storeX();
    __syncthreads();

    for (int c = 0; c < 8; c++) {
        if (c < 7) { loadW((c + 1) * 32); loadX((c + 1) * 32); }
        #pragma unroll
        for (int ks = 0; ks < 4; ks++) {
            unsigned a[2][4];
            int col = ks * 8 + tg;
            #pragma unroll
            for (int mt = 0; mt < 2; mt++) {
                int r = wm * 32 + mt * 16 + g4;
                a[mt][0] = __float_as_uint(Ws[r * 36 + col]);
                a[mt][1] = __float_as_uint(Ws[(r + 8) * 36 + col]);
                a[mt][2] = __float_as_uint(Ws[r * 36 + col + 4]);
                a[mt][3] = __float_as_uint(Ws[(r + 8) * 36 + col + 4]);
            }
            #pragma unroll
            for (int nt = 0; nt < 8; nt++) {
                int p = wn * 64 + nt * 8 + g4;
                unsigned b0 = __float_as_uint(Xs[(ks * 8 + tg) * 136 + p]);
                unsigned b1 = __float_as_uint(Xs[(ks * 8 + 4 + tg) * 136 + p]);
                mma_tf32(acc[0][nt], a[0], b0, b1);
                mma_tf32(acc[1][nt], a[1], b0, b1);
            }
        }
        __syncthreads();
        if (c < 7) { storeW(); storeX(); __syncthreads(); }
    }

    #pragma unroll
    for (int mt = 0; mt < 2; mt++) {
        int o0 = m0 + wm * 32 + mt * 16 + g4;
        float bs0 = bd[o0], bs1 = bd[o0 + 8];
        #pragma unroll
        for (int nt = 0; nt < 8; nt++) {
            int p = p0 + wn * 64 + nt * 8 + tg * 2;
            float2 v0 = make_float2(acc[mt][nt][0] + bs0, acc[mt][nt][1] + bs0);
            float2 v1 = make_float2(acc[mt][nt][2] + bs1, acc[mt][nt][3] + bs1);
            *(float2*)&fd_out[((size_t)b * CIN + o0) * HW + p]     = v0;
            *(float2*)&fd_out[((size_t)b * CIN + o0 + 8) * HW + p] = v1;
        }
    }
}

// ===========================================================================
// attn_zhat v4 (occ 3): logits via tf32 mma (warps 0-3), register softmax,
// zhat = A.y^T bf16 -> [n][pix][256c].
// ===========================================================================
#define ZA_YS  0
#define ZA_FB  (256 * 36)
#define ZA_AS  (ZA_FB + 64 * 68)
#define ZA_TOT (ZA_AS + 64 * 36)

__global__ void __launch_bounds__(256, 3) attn_zhat(
    const float* __restrict__ x, const float* __restrict__ y1,
    const float* __restrict__ fbc,
    const float* __restrict__ alpha1_p, const float* __restrict__ alpha2_p,
    __nv_bfloat16* __restrict__ zout)
{
    if (alpha2_p[0] == 0.0f) return;
    const float* y = (alpha1_p[0] == 0.0f) ? x : y1;

    extern __shared__ unsigned smu[];
    unsigned* ysp = smu + ZA_YS;           // bf16 pairs, stride 36
    float*    fb  = (float*)(smu + ZA_FB); // fp32, [ch row][pix l], stride 68
    unsigned* Asp = smu + ZA_AS;           // bf16 pairs, stride 36
    unsigned* zh  = smu + ZA_YS;           // alias, stride 132

    const int beta = blockIdx.x;
    const int n  = beta >> 8;
    const int qh = (beta >> 4) & 15, qw = beta & 15;
    const int base = (qh * 8) * 128 + qw * 8;
    const int t = threadIdx.x, lane = t & 31, w = t >> 5;
    const int g4 = lane >> 2, tg = lane & 3;

    {   // fbc tile via cp.async; y tile sync-load + bf16 pack (overlapped)
        const unsigned fba = smem_u32(fb);
        const float* fbb = fbc + (size_t)n * 64 * HW + base;
        #pragma unroll
        for (int i = 0; i < 4; i++) {
            int fi = i * 256 + t;
            int r = fi >> 4, jr = (fi >> 1) & 7, jc = (fi & 1) * 4;
            cp16(fba + (unsigned)(r * 68 + jr * 8 + jc) * 4u,
                 &fbb[(size_t)r * HW + jr * 128 + jc]);
        }
        cp_commit();

        const float* yb = y + (size_t)n * CIN * HW + base;
        #pragma unroll
        for (int i = 0; i < 16; i++) {
            int fi = i * 256 + t;
            int c = fi >> 4, jr = (fi >> 1) & 7, jc = (fi & 1) * 4;
            float4 v = *(const float4*)&yb[(size_t)c * HW + jr * 128 + jc];
            int j0 = jr * 4 + (jc >> 1);
            uint2 pk = make_uint2(pkbf(v.x, v.y), pkbf(v.z, v.w));
            *(uint2*)&ysp[c * 36 + j0] = pk;
        }
        cp_wait0();
    }
    __syncthreads();

    // ---- logits via tf32 mma (warps 0-3, 16 l-rows x 64 m each) + softmax
    if (w < 4) {
        const int l0 = w * 16;
        float acc[8][4];
        #pragma unroll
        for (int j = 0; j < 8; j++)
            #pragma unroll
            for (int q = 0; q < 4; q++) acc[j][q] = 0.f;

        #pragma unroll
        for (int ks = 0; ks < 4; ks++) {
            unsigned a[4];
            int col = ks * 8 + tg;
            a[0] = __float_as_uint(fb[col * 68 + l0 + g4]);        // fb^T[l][k]
            a[1] = __float_as_uint(fb[col * 68 + l0 + 8 + g4]);
            a[2] = __float_as_uint(fb[(col + 4) * 68 + l0 + g4]);
            a[3] = __float_as_uint(fb[(col + 4) * 68 + l0 + 8 + g4]);
            #pragma unroll
            for (int nt = 0; nt < 8; nt++) {
                int m = nt * 8 + g4;
                unsigned b0 = __float_as_uint(fb[(32 + col) * 68 + m]);
                unsigned b1 = __float_as_uint(fb[(32 + col + 4) * 68 + m]);
                mma_tf32(acc[nt], a, b0, b1);
            }
        }
        // rows: r0 = l0+g4 (acc[..][0,1]), r1 = l0+8+g4 (acc[..][2,3]);
        // lanes sharing a row differ only in tg -> shfl_xor 1,2.
        float mx0 = -1e30f, mx1 = -1e30f;
        #pragma unroll
        for (int j = 0; j < 8; j++) {
            mx0 = fmaxf(mx0, fmaxf(acc[j][0], acc[j][1]));
            mx1 = fmaxf(mx1, fmaxf(acc[j][2], acc[j][3]));
        }
        mx0 = fmaxf(mx0, __shfl_xor_sync(0xffffffff, mx0, 1));
        mx0 = fmaxf(mx0, __shfl_xor_sync(0xffffffff, mx0, 2));
        mx1 = fmaxf(mx1, __shfl_xor_sync(0xffffffff, mx1, 1));
        mx1 = fmaxf(mx1, __shfl_xor_sync(0xffffffff, mx1, 2));
        float s0 = 0.f, s1 = 0.f;
        #pragma unroll
        for (int j = 0; j < 8; j++) {
            acc[j][0] = __expf(acc[j][0] - mx0); s0 += acc[j][0];
            acc[j][1] = __expf(acc[j][1] - mx0); s0 += acc[j][1];
            acc[j][2] = __expf(acc[j][2] - mx1); s1 += acc[j][2];
            acc[j][3] = __expf(acc[j][3] - mx1); s1 += acc[j][3];
        }
        s0 += __shfl_xor_sync(0xffffffff, s0, 1);
        s0 += __shfl_xor_sync(0xffffffff, s0, 2);
        s1 += __shfl_xor_sync(0xffffffff, s1, 1);
        s1 += __shfl_xor_sync(0xffffffff, s1, 2);
        float i0 = 1.0f / s0, i1 = 1.0f / s1;
        #pragma unroll
        for (int j = 0; j < 8; j++) {
            Asp[(l0 + g4) * 36 + j * 4 + tg]     = pkbf(acc[j][0] * i0, acc[j][1] * i0);
            Asp[(l0 + 8 + g4) * 36 + j * 4 + tg] = pkbf(acc[j][2] * i1, acc[j][3] * i1);
        }
    }
    __syncthreads();

    {   // zhat = A . y^T  (M64 l, N256 c, K64 m), bf16
        const int wm = w >> 2, wc = w & 3;
        const int m0 = wm * 32, c0w = wc * 64;
        float acc[2][8][4];
        #pragma unroll
        for (int i = 0; i < 2; i++)
            #pragma unroll
            for (int j = 0; j < 8; j++)
                #pragma unroll
                for (int q = 0; q < 4; q++) acc[i][j][q] = 0.f;
        #pragma unroll
        for (int ks = 0; ks < 4; ks++) {
            unsigned a[2][4];
            int col = ks * 8 + tg;
            #pragma unroll
            for (int mt = 0; mt < 2; mt++) {
                int r = m0 + mt * 16 + g4;
                a[mt][0] = Asp[r * 36 + col];
                a[mt][1] = Asp[(r + 8) * 36 + col];
                a[mt][2] = Asp[r * 36 + col + 4];
                a[mt][3] = Asp[(r + 8) * 36 + col + 4];
            }
            #pragma unroll
            for (int nt = 0; nt < 8; nt++) {
                int c = c0w + nt * 8 + g4;
                unsigned b0 = ysp[c * 36 + col];
                unsigned b1 = ysp[c * 36 + col + 4];
                mma_bf16(acc[0][nt], a[0], b0, b1);
                mma_bf16(acc[1][nt], a[1], b0, b1);
            }
        }
        __syncthreads();                       // ysp reads done -> zh alias safe
        #pragma unroll
        for (int mt = 0; mt < 2; mt++) {
            int l0 = m0 + mt * 16 + g4;
            #pragma unroll
            for (int nt = 0; nt < 8; nt++) {
                int cp = wc * 32 + nt * 4 + tg;
                zh[l0 * 132 + cp]       = pkbf(acc[mt][nt][0], acc[mt][nt][1]);
                zh[(l0 + 8) * 132 + cp] = pkbf(acc[mt][nt][2], acc[mt][nt][3]);
            }
        }
    }
    __syncthreads();

    {   // coalesced global write: [pix][c] bf16
        unsigned* zb = (unsigned*)zout + (size_t)n * HW * 128;
        #pragma unroll
        for (int i = 0; i < 32; i++) {
            int fi = i * 256 + t;
            int l = fi >> 7, cq = fi & 127;
            int pix = base + (l >> 3) * 128 + (l & 7);
            zb[(size_t)pix * 128 + cq] = zh[l * 132 + cq];
        }
    }
}

// ===========================================================================
// conv_fe_bf (R14-best): out = alpha*(Wd.zhat + bd) + y, bf16 mma.
// Full X panel resident (cp.async), W bf16 pre-packed, cp.async double-buffered.
// Dynamic SMEM: Wsp[2][128][20] | Xs[128][132]  = 88064 B, occ 2.
// ===========================================================================
#define FE_SMEM ((2 * 128 * 20 + 128 * 132) * 4)

__global__ void __launch_bounds__(256, 2) conv_fe_bf(
    const float* __restrict__ bias,
    const __nv_bfloat16* __restrict__ zin,
    const float* __restrict__ x, const float* __restrict__ y1,
    const float* __restrict__ alpha1_p, const float* __restrict__ alpha2_p,
    float* __restrict__ out)
{
    const float alpha = alpha2_p[0];
    const float* y = (alpha1_p[0] == 0.0f) ? x : y1;

    const int b  = blockIdx.z;
    const int mi = blockIdx.x & 1;
    const int pi = blockIdx.x >> 1;
    const int m0 = mi * 128, p0 = pi * 128;
    const int t = threadIdx.x, lane = t & 31, w = t >> 5;

    if (alpha == 0.0f) {                   // identity: copy this tile
        const float* yt = y + ((size_t)b * CIN + m0) * HW + p0;
        float* ot = out + ((size_t)b * CIN + m0) * HW + p0;
        #pragma unroll
        for (int i = 0; i < 16; i++) {
            int fi = i * 256 + t;
            int o = fi >> 5, q = (fi & 31) * 4;
            *(float4*)&ot[(size_t)o * HW + q] = *(const float4*)&yt[(size_t)o * HW + q];
        }
        return;
    }

    extern __shared__ unsigned smw[];
    unsigned* Wsp = smw;                   // [2][128][20]
    unsigned* Xs  = smw + 2 * 128 * 20;    // [128][132]
    const unsigned wba = smem_u32(Wsp);
    const unsigned xba = smem_u32(Xs);

    const int wm = w >> 1, wn = w & 1;
    const int g4 = lane >> 2, tg = lane & 3;

    float acc[2][8][4];
    #pragma unroll
    for (int i = 0; i < 2; i++)
        #pragma unroll
        for (int j = 0; j < 8; j++)
            #pragma unroll
            for (int q = 0; q < 4; q++) acc[i][j][q] = 0.f;

    const unsigned* zb = (const unsigned*)zin + (size_t)b * HW * 128 + (size_t)p0 * 128;

    auto issueX = [&]() {                  // full 128x128-u32 panel
        #pragma unroll
        for (int i = 0; i < 16; i++) {
            int fi = i * 256 + t, p = fi >> 5, seg = fi & 31;
            cp16(xba + (unsigned)(p * 132 + seg * 4) * 4u, zb + (size_t)p * 128 + seg * 4);
        }
    };
    auto issueW = [&](int c, int buf) {    // W chunk: 128 rows x 16 u32
        unsigned dst = wba + (unsigned)(buf * 128 * 20) * 4u;
        #pragma unroll
        for (int i = 0; i < 2; i++) {
            int fi = i * 256 + t, o = fi >> 2, seg = fi & 3;
            cp16(dst + (unsigned)(o * 20 + seg * 4) * 4u,
                 g_wbf + (size_t)(m0 + o) * 128 + c * 16 + seg * 4);
        }
        cp_commit();
    };

    issueX();
    issueW(0, 0);                          // group contains X + W0
    cp_wait0(); __syncthreads();

    for (int c = 0; c < 8; c++) {
        if (c < 7) issueW(c + 1, (c + 1) & 1);
        const unsigned* Wd = Wsp + (c & 1) * 128 * 20;
        #pragma unroll
        for (int ks = 0; ks < 2; ks++) {
            unsigned a[2][4];
            int col = ks * 8 + tg;
            #pragma unroll
            for (int mt = 0; mt < 2; mt++) {
                int r = wm * 32 + mt * 16 + g4;
                a[mt][0] = Wd[r * 20 + col];
                a[mt][1] = Wd[(r + 8) * 20 + col];
                a[mt][2] = Wd[r * 20 + col + 4];
                a[mt][3] = Wd[(r + 8) * 20 + col + 4];
            }
            #pragma unroll
            for (int nt = 0; nt < 8; nt++) {
                int p = wn * 64 + nt * 8 + g4;
                unsigned b0 = Xs[p * 132 + c * 16 + col];
                unsigned b1 = Xs[p * 132 + c * 16 + col + 4];
                mma_bf16(acc[0][nt], a[0], b0, b1);
                mma_bf16(acc[1][nt], a[1], b0, b1);
            }
        }
        if (c < 7) { cp_wait0(); __syncthreads(); }
    }

    #pragma unroll
    for (int mt = 0; mt < 2; mt++) {
        int o0 = m0 + wm * 32 + mt * 16 + g4;
        float bs0 = bias[o0], bs1 = bias[o0 + 8];
        const float* yr0 = y + ((size_t)b * CIN + o0) * HW + p0;
        const float* yr1 = y + ((size_t)b * CIN + o0 + 8) * HW + p0;
        float* ob0 = out + ((size_t)b * CIN + o0) * HW + p0;
        float* ob1 = out + ((size_t)b * CIN + o0 + 8) * HW + p0;
        #pragma unroll
        for (int nt = 0; nt < 8; nt++) {
            int p = wn * 64 + nt * 8 + tg * 2;
            float2 yv0 = *(const float2*)&yr0[p];
            float2 yv1 = *(const float2*)&yr1[p];
            float2 v0 = make_float2(alpha * (acc[mt][nt][0] + bs0) + yv0.x,
                                    alpha * (acc[mt][nt][1] + bs0) + yv0.y);
            float2 v1 = make_float2(alpha * (acc[mt][nt][2] + bs1) + yv1.x,
                                    alpha * (acc[mt][nt][3] + bs1) + yv1.y);
            *(float2*)&ob0[p] = v0;
            *(float2*)&ob1[p] = v1;
        }
    }
}

// ---------------------------------------------------------------------------
// Stage-1 attention (general path; skipped when alpha1==0)
// ---------------------------------------------------------------------------
__global__ void __launch_bounds__(256) attn_s1(
    const float* __restrict__ x, const float* __restrict__ fbc,
    const float* __restrict__ fd, const float* __restrict__ alpha_p,
    float* __restrict__ y1)
{
    const float alpha = alpha_p[0];
    if (alpha == 0.0f) return;
    extern __shared__ float sm1f[];
    float* fbc_s = sm1f;
    float* fdc_s = fbc_s + 64 * 256;
    __nv_bfloat16* A_s = (__nv_bfloat16*)(fdc_s + 16 * 260);

    const int beta = blockIdx.x;
    const int n  = beta >> 6;
    const int ph = (beta >> 3) & 7, pw = beta & 7;
    const int t = threadIdx.x;

    for (int idx = t; idx < 64 * 256; idx += 256) {
        int r = idx >> 8, j = idx & 255;
        fbc_s[r * 256 + j] = fbc[(n * 64 + r) * HW + ((j >> 4) * 8 + ph) * 128 + (j & 15) * 8 + pw];
    }
    __syncthreads();

    float fbl[32];
    #pragma unroll
    for (int k = 0; k < 32; k++) fbl[k] = fbc_s[k * 256 + t];

    float mx = -1e30f, den = 0.f;
    for (int m = 0; m < 256; m++) {
        float s = 0.f;
        #pragma unroll
        for (int k = 0; k < 32; k++) s += fbl[k] * fbc_s[(32 + k) * 256 + m];
        if (s > mx) { den *= __expf(mx - s); mx = s; }
        den += __expf(s - mx);
    }
    float inv = 1.0f / den;
    for (int m = 0; m < 256; m++) {
        float s = 0.f;
        #pragma unroll
        for (int k = 0; k < 32; k++) s += fbl[k] * fbc_s[(32 + k) * 256 + m];
        A_s[t * 258 + m] = __float2bfloat16(__expf(s - mx) * inv);
    }
    __syncthreads();

    for (int cc = 0; cc < 16; cc++) {
        for (int idx = t; idx < 16 * 256; idx += 256) {
            int c = idx >> 8, j = idx & 255;
            fdc_s[c * 260 + j] = fd[(n * CIN + cc * 16 + c) * HW +
                                    ((j >> 4) * 8 + ph) * 128 + (j & 15) * 8 + pw];
        }
        __syncthreads();
        float acc[16] = {};
        for (int m = 0; m < 256; m++) {
            float a = __bfloat162float(A_s[t * 258 + m]);
            #pragma unroll
            for (int c = 0; c < 16; c++) acc[c] += a * fdc_s[c * 260 + m];
        }
        const int pix = ((t >> 4) * 8 + ph) * 128 + (t & 15) * 8 + pw;
        #pragma unroll
        for (int c = 0; c < 16; c++) {
            int off = (n * CIN + cc * 16 + c) * HW + pix;
            y1[off] = alpha * acc[c] + x[off];
        }
        __syncthreads();
    }
}

// ---------------------------------------------------------------------------
// Host launcher — 5 launches total
// ---------------------------------------------------------------------------
extern "C" void kernel_launch(void* const* d_in, const int* in_sizes, int n_in,
                              void* d_out, int out_size)
{
    const float* x      = (const float*)d_in[0];
    const float* Wb1    = (const float*)d_in[1];
    const float* bb1    = (const float*)d_in[2];
    const float* Wc1    = (const float*)d_in[3];
    const float* bc1    = (const float*)d_in[4];
    const float* Wd1    = (const float*)d_in[5];
    const float* bd1    = (const float*)d_in[6];
    const float* alpha1 = (const float*)d_in[7];
    const float* Wb2    = (const float*)d_in[8];
    const float* bb2    = (const float*)d_in[9];
    const float* Wc2    = (const float*)d_in[10];
    const float* bc2    = (const float*)d_in[11];
    const float* Wd2    = (const float*)d_in[12];
    const float* bd2    = (const float*)d_in[13];
    const float* alpha2 = (const float*)d_in[14];
    float* out = (float*)d_out;

    cudaFuncSetAttribute(attn_s1, cudaFuncAttributeMaxDynamicSharedMemorySize, 214272);
    cudaFuncSetAttribute(attn_zhat, cudaFuncAttributeMaxDynamicSharedMemorySize, ZA_TOT * 4);
    cudaFuncSetAttribute(conv_fbc_tc, cudaFuncAttributeMaxDynamicSharedMemorySize, FBC_SMEM);
    cudaFuncSetAttribute(stage1_convs, cudaFuncAttributeMaxDynamicSharedMemorySize, FBC_SMEM);
    cudaFuncSetAttribute(conv_fe_bf, cudaFuncAttributeMaxDynamicSharedMemorySize, FE_SMEM);

    float *y1p, *fdp, *fbcp;
    cudaGetSymbolAddress((void**)&y1p,  g_y1);
    cudaGetSymbolAddress((void**)&fdp,  g_fd);
    cudaGetSymbolAddress((void**)&fbcp, g_fbc);

    // ---- Stage 1 (general path; both kernels self-skip when alpha1==0) --
    stage1_convs<<<dim3(384, 1, NIMG), 256, FBC_SMEM>>>(
        Wb1, bb1, Wc1, bc1, Wd1, bd1, x, alpha1, fbcp, fdp);
    attn_s1<<<512, 256, 214272>>>(x, fbcp, fdp, alpha1, y1p);

    // ---- Stage 2 (z==8 slice of conv_fbc packs Wd2 -> g_wbf) -------------
    conv_fbc_tc<<<dim3(128, 1, 9), 256, FBC_SMEM>>>(
        Wb2, bb2, Wc2, bc2, x, y1p, alpha1, alpha2, Wd2, fbcp);
    attn_zhat<<<2048, 256, ZA_TOT * 4>>>(x, y1p, fbcp, alpha1, alpha2, (__nv_bfloat16*)fdp);
    conv_fe_bf<<<dim3(256, 1, NIMG), 256, FE_SMEM>>>(bd2, (const __nv_bfloat16*)fdp,
                                                     x, y1p, alpha1, alpha2, out);
}

// round 17
// speedup vs baseline: 1.2912x; 1.0200x over previous
#include <cuda_runtime.h>
#include <cuda_bf16.h>

#define NIMG 8
#define CIN  256
#define HW   16384      // 128*128
#define C8   32

// ---------------------------------------------------------------------------
// Scratch
// ---------------------------------------------------------------------------
__device__ float    g_y1 [NIMG * CIN * HW];
__device__ float    g_fd [NIMG * CIN * HW];   // stage-1 fd / stage-2 zhat (bf16 view)
__device__ float    g_fbc[NIMG * 64  * HW];
__device__ unsigned g_wbf[CIN * 128];         // Wd2 as bf16 pairs [o][k/2]

// ---------------------------------------------------------------------------
// Helpers
// ---------------------------------------------------------------------------
__device__ __forceinline__ unsigned f2tf(float f) {
    unsigned u; asm("cvt.rna.tf32.f32 %0, %1;" : "=r"(u) : "f"(f)); return u;
}
__device__ __forceinline__ void mma_tf32(float* c, const unsigned* a, unsigned b0, unsigned b1) {
    asm volatile("mma.sync.aligned.m16n8k8.row.col.f32.tf32.tf32.f32 "
                 "{%0,%1,%2,%3}, {%4,%5,%6,%7}, {%8,%9}, {%0,%1,%2,%3};"
                 : "+f"(c[0]), "+f"(c[1]), "+f"(c[2]), "+f"(c[3])
                 : "r"(a[0]), "r"(a[1]), "r"(a[2]), "r"(a[3]), "r"(b0), "r"(b1));
}
__device__ __forceinline__ void mma_bf16(float* c, const unsigned* a, unsigned b0, unsigned b1) {
    asm volatile("mma.sync.aligned.m16n8k16.row.col.f32.bf16.bf16.f32 "
                 "{%0,%1,%2,%3}, {%4,%5,%6,%7}, {%8,%9}, {%0,%1,%2,%3};"
                 : "+f"(c[0]), "+f"(c[1]), "+f"(c[2]), "+f"(c[3])
                 : "r"(a[0]), "r"(a[1]), "r"(a[2]), "r"(a[3]), "r"(b0), "r"(b1));
}
__device__ __forceinline__ unsigned pkbf(float lo, float hi) {
    __nv_bfloat162 h = __floats2bfloat162_rn(lo, hi);
    return *(unsigned*)&h;
}
__device__ __forceinline__ void cp16(unsigned dst, const void* src) {
    asm volatile("cp.async.cg.shared.global [%0], [%1], 16;" :: "r"(dst), "l"(src));
}
__device__ __forceinline__ void cp_commit() { asm volatile("cp.async.commit_group;"); }
__device__ __forceinline__ void cp_wait0()  { asm volatile("cp.async.wait_group 0;"); }

__device__ __forceinline__ unsigned smem_u32(const void* p) {
    unsigned a;
    asm("{ .reg .u64 t; cvta.to.shared.u64 t, %1; cvt.u32.u64 %0, t; }" : "=r"(a) : "l"(p));
    return a;
}

// ===========================================================================
// conv_fbc_tc: fbc = [Wb;Wc].in + [bb;bc]   (M=64, tf32, cp.async both ops)
// z==8 blocks pack Wfe -> g_wbf (bf16 pairs).
// Dynamic SMEM: Ws[2][64][36] | Xs[2][32][136]  = 53248 B
// ===========================================================================
#define FBC_SMEM ((2 * 64 * 36 + 2 * 32 * 136) * 4)

__device__ __forceinline__ void fbc_body(
    const float* __restrict__ Wb, const float* __restrict__ bb,
    const float* __restrict__ Wc, const float* __restrict__ bc,
    const float* __restrict__ in, float* __restrict__ out,
    int b, int p0, float* smf)
{
    float* Wbuf = smf;
    float* Xbuf = smf + 2 * 64 * 36;
    const unsigned wba = smem_u32(Wbuf);
    const unsigned xba = smem_u32(Xbuf);

    const int t = threadIdx.x, lane = t & 31, w = t >> 5;
    const int wm = w >> 2, wn = w & 3;
    const int g4 = lane >> 2, tg = lane & 3;

    float acc[2][4][4] = {};
    const float* inb = in + (size_t)b * CIN * HW + p0;

    auto issue = [&](int k0, int buf) {
        unsigned wd = wba + (unsigned)(buf * 64 * 36) * 4u;
        #pragma unroll
        for (int i = 0; i < 2; i++) {
            int fi = i * 256 + t, o = fi >> 3, k4 = (fi & 7) * 4;
            const float* src = (o < 32) ? &Wb[o * 256 + k0 + k4]
                                        : &Wc[(o - 32) * 256 + k0 + k4];
            cp16(wd + (unsigned)(o * 36 + k4) * 4u, src);
        }
        unsigned xd = xba + (unsigned)(buf * 32 * 136) * 4u;
        #pragma unroll
        for (int i = 0; i < 4; i++) {
            int fi = i * 256 + t, k = fi >> 5, seg = fi & 31;
            cp16(xd + (unsigned)(k * 136 + seg * 4) * 4u,
                 inb + (size_t)(k0 + k) * HW + seg * 4);
        }
        cp_commit();
    };

    issue(0, 0);
    cp_wait0(); __syncthreads();

    for (int c = 0; c < 8; c++) {
        if (c < 7) issue((c + 1) * 32, (c + 1) & 1);
        const float* Wd = Wbuf + (c & 1) * 64 * 36;
        const float* Xd = Xbuf + (c & 1) * 32 * 136;
        #pragma unroll
        for (int ks = 0; ks < 4; ks++) {
            unsigned a[2][4];
            int col = ks * 8 + tg;
            #pragma unroll
            for (int mt = 0; mt < 2; mt++) {
                int r = wm * 32 + mt * 16 + g4;
                a[mt][0] = __float_as_uint(Wd[r * 36 + col]);
                a[mt][1] = __float_as_uint(Wd[(r + 8) * 36 + col]);
                a[mt][2] = __float_as_uint(Wd[r * 36 + col + 4]);
                a[mt][3] = __float_as_uint(Wd[(r + 8) * 36 + col + 4]);
            }
            #pragma unroll
            for (int nt = 0; nt < 4; nt++) {
                int p = wn * 32 + nt * 8 + g4;
                unsigned b0 = __float_as_uint(Xd[(ks * 8 + tg) * 136 + p]);
                unsigned b1 = __float_as_uint(Xd[(ks * 8 + 4 + tg) * 136 + p]);
                mma_tf32(acc[0][nt], a[0], b0, b1);
                mma_tf32(acc[1][nt], a[1], b0, b1);
            }
        }
        if (c < 7) { cp_wait0(); __syncthreads(); }
    }

    #pragma unroll
    for (int mt = 0; mt < 2; mt++) {
        int o0 = wm * 32 + mt * 16 + g4, o1 = o0 + 8;
        float bs0 = (o0 < 32) ? bb[o0] : bc[o0 - 32];
        float bs1 = (o1 < 32) ? bb[o1] : bc[o1 - 32];
        #pragma unroll
        for (int nt = 0; nt < 4; nt++) {
            int p = p0 + wn * 32 + nt * 8 + tg * 2;
            *(float2*)&out[((size_t)b * 64 + o0) * HW + p] =
                make_float2(acc[mt][nt][0] + bs0, acc[mt][nt][1] + bs0);
            *(float2*)&out[((size_t)b * 64 + o1) * HW + p] =
                make_float2(acc[mt][nt][2] + bs1, acc[mt][nt][3] + bs1);
        }
    }
}

__global__ void __launch_bounds__(256, 3) conv_fbc_tc(
    const float* __restrict__ Wb, const float* __restrict__ bb,
    const float* __restrict__ Wc, const float* __restrict__ bc,
    const float* __restrict__ inA, const float* __restrict__ inB,
    const float* __restrict__ sel, const float* __restrict__ guard,
    const float* __restrict__ Wfe,
    float* __restrict__ out)
{
    if (guard[0] == 0.0f) return;
    if (blockIdx.z == 8) {                 // folded wcvt
        int idx = blockIdx.x * 256 + threadIdx.x;
        int o = idx >> 7, kp = idx & 127;
        g_wbf[idx] = pkbf(Wfe[o * 256 + kp * 2], Wfe[o * 256 + kp * 2 + 1]);
        return;
    }
    extern __shared__ float smf[];
    const float* in = (sel[0] == 0.0f) ? inA : inB;
    fbc_body(Wb, bb, Wc, bc, in, out, blockIdx.z, blockIdx.x * 128, smf);
}

// ===========================================================================
// stage1_convs: merged stage-1 fbc conv (x<128) + fd conv (x>=128).
// General path only; skips entirely when alpha1 == 0.
// ===========================================================================
__global__ void __launch_bounds__(256, 3) stage1_convs(
    const float* __restrict__ Wb, const float* __restrict__ bb,
    const float* __restrict__ Wc, const float* __restrict__ bc,
    const float* __restrict__ Wd, const float* __restrict__ bd,
    const float* __restrict__ x, const float* __restrict__ alpha1,
    float* __restrict__ fbc_out, float* __restrict__ fd_out)
{
    if (alpha1[0] == 0.0f) return;
    extern __shared__ float smf[];
    const int b = blockIdx.z;

    if (blockIdx.x < 128) {                // fbc path
        fbc_body(Wb, bb, Wc, bc, x, fbc_out, b, blockIdx.x * 128, smf);
        return;
    }

    const int idx = blockIdx.x - 128;      // 0..255
    const int m0 = (idx & 1) * 128, p0 = (idx >> 1) * 128;

    float* Ws = smf;                       // [128][36]
    float* Xs = smf + 128 * 36;            // [32][136]

    const int t = threadIdx.x, lane = t & 31, w = t >> 5;
    const int wm = w >> 1, wn = w & 1;
    const int g4 = lane >> 2, tg = lane & 3;

    float acc[2][8][4];
    #pragma unroll
    for (int i = 0; i < 2; i++)
        #pragma unroll
        for (int j = 0; j < 8; j++)
            #pragma unroll
            for (int q = 0; q < 4; q++) acc[i][j][q] = 0.f;

    const float* inb = x + (size_t)b * CIN * HW + p0;
    float4 wreg[4], xreg[4];

    auto loadW = [&](int k0) {
        #pragma unroll
        for (int i = 0; i < 4; i++) {
            int fi = i * 256 + t, o = fi >> 3, k4 = (fi & 7) * 4;
            wreg[i] = *(const float4*)&Wd[(m0 + o) * CIN + k0 + k4];
        }
    };
    auto loadX = [&](int k0) {
        #pragma unroll
        for (int i = 0; i < 4; i++) {
            int fi = i * 256 + t, k = fi >> 5, p4 = (fi & 31) * 4;
            xreg[i] = *(const float4*)&inb[(size_t)(k0 + k) * HW + p4];
        }
    };
    auto storeW = [&]() {
        #pragma unroll
        for (int i = 0; i < 4; i++) {
            int fi = i * 256 + t, o = fi >> 3, k4 = (fi & 7) * 4;
            float4 v = wreg[i];
            Ws[o * 36 + k4 + 0] = __uint_as_float(f2tf(v.x));
            Ws[o * 36 + k4 + 1] = __uint_as_float(f2tf(v.y));
            Ws[o * 36 + k4 + 2] = __uint_as_float(f2tf(v.z));
            Ws[o * 36 + k4 + 3] = __uint_as_float(f2tf(v.w));
        }
    };
    auto storeX = [&]() {
        #pragma unroll
        for (int i = 0; i < 4; i++) {
            int fi = i * 256 + t, k = fi >> 5, p4 = (fi & 31) * 4;
            float4 v = xreg[i];
            Xs[k * 136 + p4 + 0] = __uint_as_float(f2tf(v.x));
            Xs[k * 136 + p4 + 1] = __uint_as_float(f2tf(v.y));
            Xs[k * 136 + p4 + 2] = __uint_as_float(f2tf(v.z));
            Xs[k * 136 + p4 + 3] = __uint_as_float(f2tf(v.w));
        }
    };

    loadW(0); loadX(0);
    storeW(); storeX();
    __syncthreads();

    for (int c = 0; c < 8; c++) {
        if (c < 7) { loadW((c + 1) * 32); loadX((c + 1) * 32); }
        #pragma unroll
        for (int ks = 0; ks < 4; ks++) {
            unsigned a[2][4];
            int col = ks * 8 + tg;
            #pragma unroll
            for (int mt = 0; mt < 2; mt++) {
                int r = wm * 32 + mt * 16 + g4;
                a[mt][0] = __float_as_uint(Ws[r * 36 + col]);
                a[mt][1] = __float_as_uint(Ws[(r + 8) * 36 + col]);
                a[mt][2] = __float_as_uint(Ws[r * 36 + col + 4]);
                a[mt][3] = __float_as_uint(Ws[(r + 8) * 36 + col + 4]);
            }
            #pragma unroll
            for (int nt = 0; nt < 8; nt++) {
                int p = wn * 64 + nt * 8 + g4;
                unsigned b0 = __float_as_uint(Xs[(ks * 8 + tg) * 136 + p]);
                unsigned b1 = __float_as_uint(Xs[(ks * 8 + 4 + tg) * 136 + p]);
                mma_tf32(acc[0][nt], a[0], b0, b1);
                mma_tf32(acc[1][nt], a[1], b0, b1);
            }
        }
        __syncthreads();
        if (c < 7) { storeW(); storeX(); __syncthreads(); }
    }

    #pragma unroll
    for (int mt = 0; mt < 2; mt++) {
        int o0 = m0 + wm * 32 + mt * 16 + g4;
        float bs0 = bd[o0], bs1 = bd[o0 + 8];
        #pragma unroll
        for (int nt = 0; nt < 8; nt++) {
            int p = p0 + wn * 64 + nt * 8 + tg * 2;
            float2 v0 = make_float2(acc[mt][nt][0] + bs0, acc[mt][nt][1] + bs0);
            float2 v1 = make_float2(acc[mt][nt][2] + bs1, acc[mt][nt][3] + bs1);
            *(float2*)&fd_out[((size_t)b * CIN + o0) * HW + p]     = v0;
            *(float2*)&fd_out[((size_t)b * CIN + o0 + 8) * HW + p] = v1;
        }
    }
}

// ===========================================================================
// attn_zhat v5 (occ 3, warp-specialized front end):
//   warps 0-3: fbc cp.async -> logits (tf32 mma) -> softmax -> Asp
//   warps 4-7: concurrently load + bf16-pack the y tile into ysp
//   then all:  zhat = A.y^T (bf16 mma) -> [n][pix][256c]
// ===========================================================================
#define ZA_YS  0
#define ZA_FB  (256 * 36)
#define ZA_AS  (ZA_FB + 64 * 68)
#define ZA_TOT (ZA_AS + 64 * 36)

__global__ void __launch_bounds__(256, 3) attn_zhat(
    const float* __restrict__ x, const float* __restrict__ y1,
    const float* __restrict__ fbc,
    const float* __restrict__ alpha1_p, const float* __restrict__ alpha2_p,
    __nv_bfloat16* __restrict__ zout)
{
    if (alpha2_p[0] == 0.0f) return;
    const float* y = (alpha1_p[0] == 0.0f) ? x : y1;

    extern __shared__ unsigned smu[];
    unsigned* ysp = smu + ZA_YS;           // bf16 pairs, stride 36
    float*    fb  = (float*)(smu + ZA_FB); // fp32, [ch row][pix l], stride 68
    unsigned* Asp = smu + ZA_AS;           // bf16 pairs, stride 36
    unsigned* zh  = smu + ZA_YS;           // alias, stride 132

    const int beta = blockIdx.x;
    const int n  = beta >> 8;
    const int qh = (beta >> 4) & 15, qw = beta & 15;
    const int base = (qh * 8) * 128 + qw * 8;
    const int t = threadIdx.x, lane = t & 31, w = t >> 5;
    const int g4 = lane >> 2, tg = lane & 3;

    if (w < 4) {
        // ---- producer/logits group: fbc cp.async + logits + softmax -----
        const unsigned fba = smem_u32(fb);
        const float* fbb = fbc + (size_t)n * 64 * HW + base;
        #pragma unroll
        for (int i = 0; i < 8; i++) {      // 1024 float4, 128 threads
            int fi = i * 128 + t;
            int r = fi >> 4, jr = (fi >> 1) & 7, jc = (fi & 1) * 4;
            cp16(fba + (unsigned)(r * 68 + jr * 8 + jc) * 4u,
                 &fbb[(size_t)r * HW + jr * 128 + jc]);
        }
        cp_commit();
        cp_wait0();
        asm volatile("bar.sync 1, 128;" ::: "memory");   // all fbc copies visible

        const int l0 = w * 16;
        float acc[8][4];
        #pragma unroll
        for (int j = 0; j < 8; j++)
            #pragma unroll
            for (int q = 0; q < 4; q++) acc[j][q] = 0.f;

        #pragma unroll
        for (int ks = 0; ks < 4; ks++) {
            unsigned a[4];
            int col = ks * 8 + tg;
            a[0] = __float_as_uint(fb[col * 68 + l0 + g4]);
            a[1] = __float_as_uint(fb[col * 68 + l0 + 8 + g4]);
            a[2] = __float_as_uint(fb[(col + 4) * 68 + l0 + g4]);
            a[3] = __float_as_uint(fb[(col + 4) * 68 + l0 + 8 + g4]);
            #pragma unroll
            for (int nt = 0; nt < 8; nt++) {
                int m = nt * 8 + g4;
                unsigned b0 = __float_as_uint(fb[(32 + col) * 68 + m]);
                unsigned b1 = __float_as_uint(fb[(32 + col + 4) * 68 + m]);
                mma_tf32(acc[nt], a, b0, b1);
            }
        }
        float mx0 = -1e30f, mx1 = -1e30f;
        #pragma unroll
        for (int j = 0; j < 8; j++) {
            mx0 = fmaxf(mx0, fmaxf(acc[j][0], acc[j][1]));
            mx1 = fmaxf(mx1, fmaxf(acc[j][2], acc[j][3]));
        }
        mx0 = fmaxf(mx0, __shfl_xor_sync(0xffffffff, mx0, 1));
        mx0 = fmaxf(mx0, __shfl_xor_sync(0xffffffff, mx0, 2));
        mx1 = fmaxf(mx1, __shfl_xor_sync(0xffffffff, mx1, 1));
        mx1 = fmaxf(mx1, __shfl_xor_sync(0xffffffff, mx1, 2));
        float s0 = 0.f, s1 = 0.f;
        #pragma unroll
        for (int j = 0; j < 8; j++) {
            acc[j][0] = __expf(acc[j][0] - mx0); s0 += acc[j][0];
            acc[j][1] = __expf(acc[j][1] - mx0); s0 += acc[j][1];
            acc[j][2] = __expf(acc[j][2] - mx1); s1 += acc[j][2];
            acc[j][3] = __expf(acc[j][3] - mx1); s1 += acc[j][3];
        }
        s0 += __shfl_xor_sync(0xffffffff, s0, 1);
        s0 += __shfl_xor_sync(0xffffffff, s0, 2);
        s1 += __shfl_xor_sync(0xffffffff, s1, 1);
        s1 += __shfl_xor_sync(0xffffffff, s1, 2);
        float i0 = 1.0f / s0, i1 = 1.0f / s1;
        #pragma unroll
        for (int j = 0; j < 8; j++) {
            Asp[(l0 + g4) * 36 + j * 4 + tg]     = pkbf(acc[j][0] * i0, acc[j][1] * i0);
            Asp[(l0 + 8 + g4) * 36 + j * 4 + tg] = pkbf(acc[j][2] * i1, acc[j][3] * i1);
        }
    } else {
        // ---- y group: load + bf16-pack the full y tile ------------------
        const float* yb = y + (size_t)n * CIN * HW + base;
        const int t2 = t - 128;
        #pragma unroll
        for (int i = 0; i < 32; i++) {     // 4096 float4, 128 threads
            int fi = i * 128 + t2;
            int c = fi >> 4, jr = (fi >> 1) & 7, jc = (fi & 1) * 4;
            float4 v = *(const float4*)&yb[(size_t)c * HW + jr * 128 + jc];
            int j0 = jr * 4 + (jc >> 1);
            uint2 pk = make_uint2(pkbf(v.x, v.y), pkbf(v.z, v.w));
            *(uint2*)&ysp[c * 36 + j0] = pk;
        }
    }
    __syncthreads();

    {   // zhat = A . y^T  (M64 l, N256 c, K64 m), bf16
        const int wm = w >> 2, wc = w & 3;
        const int m0 = wm * 32, c0w = wc * 64;
        float acc[2][8][4];
        #pragma unroll
        for (int i = 0; i < 2; i++)
            #pragma unroll
            for (int j = 0; j < 8; j++)
                #pragma unroll
                for (int q = 0; q < 4; q++) acc[i][j][q] = 0.f;
        #pragma unroll
        for (int ks = 0; ks < 4; ks++) {
            unsigned a[2][4];
            int col = ks * 8 + tg;
            #pragma unroll
            for (int mt = 0; mt < 2; mt++) {
                int r = m0 + mt * 16 + g4;
                a[mt][0] = Asp[r * 36 + col];
                a[mt][1] = Asp[(r + 8) * 36 + col];
                a[mt][2] = Asp[r * 36 + col + 4];
                a[mt][3] = Asp[(r + 8) * 36 + col + 4];
            }
            #pragma unroll
            for (int nt = 0; nt < 8; nt++) {
                int c = c0w + nt * 8 + g4;
                unsigned b0 = ysp[c * 36 + col];
                unsigned b1 = ysp[c * 36 + col + 4];
                mma_bf16(acc[0][nt], a[0], b0, b1);
                mma_bf16(acc[1][nt], a[1], b0, b1);
            }
        }
        __syncthreads();                       // ysp reads done -> zh alias safe
        #pragma unroll
        for (int mt = 0; mt < 2; mt++) {
            int l0 = m0 + mt * 16 + g4;
            #pragma unroll
            for (int nt = 0; nt < 8; nt++) {
                int cp = wc * 32 + nt * 4 + tg;
                zh[l0 * 132 + cp]       = pkbf(acc[mt][nt][0], acc[mt][nt][1]);
                zh[(l0 + 8) * 132 + cp] = pkbf(acc[mt][nt][2], acc[mt][nt][3]);
            }
        }
    }
    __syncthreads();

    {   // coalesced global write: [pix][c] bf16
        unsigned* zb = (unsigned*)zout + (size_t)n * HW * 128;
        #pragma unroll
        for (int i = 0; i < 32; i++) {
            int fi = i * 256 + t;
            int l = fi >> 7, cq = fi & 127;
            int pix = base + (l >> 3) * 128 + (l & 7);
            zb[(size_t)pix * 128 + cq] = zh[l * 132 + cq];
        }
    }
}

// ===========================================================================
// conv_fe_bf (R14-best): out = alpha*(Wd.zhat + bd) + y, bf16 mma.
// Full X panel resident (cp.async), W bf16 pre-packed, cp.async double-buffered.
// Dynamic SMEM: Wsp[2][128][20] | Xs[128][132]  = 88064 B, occ 2.
// ===========================================================================
#define FE_SMEM ((2 * 128 * 20 + 128 * 132) * 4)

__global__ void __launch_bounds__(256, 2) conv_fe_bf(
    const float* __restrict__ bias,
    const __nv_bfloat16* __restrict__ zin,
    const float* __restrict__ x, const float* __restrict__ y1,
    const float* __restrict__ alpha1_p, const float* __restrict__ alpha2_p,
    float* __restrict__ out)
{
    const float alpha = alpha2_p[0];
    const float* y = (alpha1_p[0] == 0.0f) ? x : y1;

    const int b  = blockIdx.z;
    const int mi = blockIdx.x & 1;
    const int pi = blockIdx.x >> 1;
    const int m0 = mi * 128, p0 = pi * 128;
    const int t = threadIdx.x, lane = t & 31, w = t >> 5;

    if (alpha == 0.0f) {                   // identity: copy this tile
        const float* yt = y + ((size_t)b * CIN + m0) * HW + p0;
        float* ot = out + ((size_t)b * CIN + m0) * HW + p0;
        #pragma unroll
        for (int i = 0; i < 16; i++) {
            int fi = i * 256 + t;
            int o = fi >> 5, q = (fi & 31) * 4;
            *(float4*)&ot[(size_t)o * HW + q] = *(const float4*)&yt[(size_t)o * HW + q];
        }
        return;
    }

    extern __shared__ unsigned smw[];
    unsigned* Wsp = smw;                   // [2][128][20]
    unsigned* Xs  = smw + 2 * 128 * 20;    // [128][132]
    const unsigned wba = smem_u32(Wsp);
    const unsigned xba = smem_u32(Xs);

    const int wm = w >> 1, wn = w & 1;
    const int g4 = lane >> 2, tg = lane & 3;

    float acc[2][8][4];
    #pragma unroll
    for (int i = 0; i < 2; i++)
        #pragma unroll
        for (int j = 0; j < 8; j++)
            #pragma unroll
            for (int q = 0; q < 4; q++) acc[i][j][q] = 0.f;

    const unsigned* zb = (const unsigned*)zin + (size_t)b * HW * 128 + (size_t)p0 * 128;

    auto issueX = [&]() {                  // full 128x128-u32 panel
        #pragma unroll
        for (int i = 0; i < 16; i++) {
            int fi = i * 256 + t, p = fi >> 5, seg = fi & 31;
            cp16(xba + (unsigned)(p * 132 + seg * 4) * 4u, zb + (size_t)p * 128 + seg * 4);
        }
    };
    auto issueW = [&](int c, int buf) {    // W chunk: 128 rows x 16 u32
        unsigned dst = wba + (unsigned)(buf * 128 * 20) * 4u;
        #pragma unroll
        for (int i = 0; i < 2; i++) {
            int fi = i * 256 + t, o = fi >> 2, seg = fi & 3;
            cp16(dst + (unsigned)(o * 20 + seg * 4) * 4u,
                 g_wbf + (size_t)(m0 + o) * 128 + c * 16 + seg * 4);
        }
        cp_commit();
    };

    issueX();
    issueW(0, 0);                          // group contains X + W0
    cp_wait0(); __syncthreads();

    for (int c = 0; c < 8; c++) {
        if (c < 7) issueW(c + 1, (c + 1) & 1);
        const unsigned* Wd = Wsp + (c & 1) * 128 * 20;
        #pragma unroll
        for (int ks = 0; ks < 2; ks++) {
            unsigned a[2][4];
            int col = ks * 8 + tg;
            #pragma unroll
            for (int mt = 0; mt < 2; mt++) {
                int r = wm * 32 + mt * 16 + g4;
                a[mt][0] = Wd[r * 20 + col];
                a[mt][1] = Wd[(r + 8) * 20 + col];
                a[mt][2] = Wd[r * 20 + col + 4];
                a[mt][3] = Wd[(r + 8) * 20 + col + 4];
            }
            #pragma unroll
            for (int nt = 0; nt < 8; nt++) {
                int p = wn * 64 + nt * 8 + g4;
                unsigned b0 = Xs[p * 132 + c * 16 + col];
                unsigned b1 = Xs[p * 132 + c * 16 + col + 4];
                mma_bf16(acc[0][nt], a[0], b0, b1);
                mma_bf16(acc[1][nt], a[1], b0, b1);
            }
        }
        if (c < 7) { cp_wait0(); __syncthreads(); }
    }

    #pragma unroll
    for (int mt = 0; mt < 2; mt++) {
        int o0 = m0 + wm * 32 + mt * 16 + g4;
        float bs0 = bias[o0], bs1 = bias[o0 + 8];
        const float* yr0 = y + ((size_t)b * CIN + o0) * HW + p0;
        const float* yr1 = y + ((size_t)b * CIN + o0 + 8) * HW + p0;
        float* ob0 = out + ((size_t)b * CIN + o0) * HW + p0;
        float* ob1 = out + ((size_t)b * CIN + o0 + 8) * HW + p0;
        #pragma unroll
        for (int nt = 0; nt < 8; nt++) {
            int p = wn * 64 + nt * 8 + tg * 2;
            float2 yv0 = *(const float2*)&yr0[p];
            float2 yv1 = *(const float2*)&yr1[p];
            float2 v0 = make_float2(alpha * (acc[mt][nt][0] + bs0) + yv0.x,
                                    alpha * (acc[mt][nt][1] + bs0) + yv0.y);
            float2 v1 = make_float2(alpha * (acc[mt][nt][2] + bs1) + yv1.x,
                                    alpha * (acc[mt][nt][3] + bs1) + yv1.y);
            *(float2*)&ob0[p] = v0;
            *(float2*)&ob1[p] = v1;
        }
    }
}

// ---------------------------------------------------------------------------
// Stage-1 attention (general path; skipped when alpha1==0)
// ---------------------------------------------------------------------------
__global__ void __launch_bounds__(256) attn_s1(
    const float* __restrict__ x, const float* __restrict__ fbc,
    const float* __restrict__ fd, const float* __restrict__ alpha_p,
    float* __restrict__ y1)
{
    const float alpha = alpha_p[0];
    if (alpha == 0.0f) return;
    extern __shared__ float sm1f[];
    float* fbc_s = sm1f;
    float* fdc_s = fbc_s + 64 * 256;
    __nv_bfloat16* A_s = (__nv_bfloat16*)(fdc_s + 16 * 260);

    const int beta = blockIdx.x;
    const int n  = beta >> 6;
    const int ph = (beta >> 3) & 7, pw = beta & 7;
    const int t = threadIdx.x;

    for (int idx = t; idx < 64 * 256; idx += 256) {
        int r = idx >> 8, j = idx & 255;
        fbc_s[r * 256 + j] = fbc[(n * 64 + r) * HW + ((j >> 4) * 8 + ph) * 128 + (j & 15) * 8 + pw];
    }
    __syncthreads();

    float fbl[32];
    #pragma unroll
    for (int k = 0; k < 32; k++) fbl[k] = fbc_s[k * 256 + t];

    float mx = -1e30f, den = 0.f;
    for (int m = 0; m < 256; m++) {
        float s = 0.f;
        #pragma unroll
        for (int k = 0; k < 32; k++) s += fbl[k] * fbc_s[(32 + k) * 256 + m];
        if (s > mx) { den *= __expf(mx - s); mx = s; }
        den += __expf(s - mx);
    }
    float inv = 1.0f / den;
    for (int m = 0; m < 256; m++) {
        float s = 0.f;
        #pragma unroll
        for (int k = 0; k < 32; k++) s += fbl[k] * fbc_s[(32 + k) * 256 + m];
        A_s[t * 258 + m] = __float2bfloat16(__expf(s - mx) * inv);
    }
    __syncthreads();

    for (int cc = 0; cc < 16; cc++) {
        for (int idx = t; idx < 16 * 256; idx += 256) {
            int c = idx >> 8, j = idx & 255;
            fdc_s[c * 260 + j] = fd[(n * CIN + cc * 16 + c) * HW +
                                    ((j >> 4) * 8 + ph) * 128 + (j & 15) * 8 + pw];
        }
        __syncthreads();
        float acc[16] = {};
        for (int m = 0; m < 256; m++) {
            float a = __bfloat162float(A_s[t * 258 + m]);
            #pragma unroll
            for (int c = 0; c < 16; c++) acc[c] += a * fdc_s[c * 260 + m];
        }
        const int pix = ((t >> 4) * 8 + ph) * 128 + (t & 15) * 8 + pw;
        #pragma unroll
        for (int c = 0; c < 16; c++) {
            int off = (n * CIN + cc * 16 + c) * HW + pix;
            y1[off] = alpha * acc[c] + x[off];
        }
        __syncthreads();
    }
}

// ---------------------------------------------------------------------------
// Host launcher — 5 launches total
// ---------------------------------------------------------------------------
extern "C" void kernel_launch(void* const* d_in, const int* in_sizes, int n_in,
                              void* d_out, int out_size)
{
    const float* x      = (const float*)d_in[0];
    const float* Wb1    = (const float*)d_in[1];
    const float* bb1    = (const float*)d_in[2];
    const float* Wc1    = (const float*)d_in[3];
    const float* bc1    = (const float*)d_in[4];
    const float* Wd1    = (const float*)d_in[5];
    const float* bd1    = (const float*)d_in[6];
    const float* alpha1 = (const float*)d_in[7];
    const float* Wb2    = (const float*)d_in[8];
    const float* bb2    = (const float*)d_in[9];
    const float* Wc2    = (const float*)d_in[10];
    const float* bc2    = (const float*)d_in[11];
    const float* Wd2    = (const float*)d_in[12];
    const float* bd2    = (const float*)d_in[13];
    const float* alpha2 = (const float*)d_in[14];
    float* out = (float*)d_out;

    cudaFuncSetAttribute(attn_s1, cudaFuncAttributeMaxDynamicSharedMemorySize, 214272);
    cudaFuncSetAttribute(attn_zhat, cudaFuncAttributeMaxDynamicSharedMemorySize, ZA_TOT * 4);
    cudaFuncSetAttribute(conv_fbc_tc, cudaFuncAttributeMaxDynamicSharedMemorySize, FBC_SMEM);
    cudaFuncSetAttribute(stage1_convs, cudaFuncAttributeMaxDynamicSharedMemorySize, FBC_SMEM);
    cudaFuncSetAttribute(conv_fe_bf, cudaFuncAttributeMaxDynamicSharedMemorySize, FE_SMEM);

    float *y1p, *fdp, *fbcp;
    cudaGetSymbolAddress((void**)&y1p,  g_y1);
    cudaGetSymbolAddress((void**)&fdp,  g_fd);
    cudaGetSymbolAddress((void**)&fbcp, g_fbc);

    // ---- Stage 1 (general path; both kernels self-skip when alpha1==0) --
    stage1_convs<<<dim3(384, 1, NIMG), 256, FBC_SMEM>>>(
        Wb1, bb1, Wc1, bc1, Wd1, bd1, x, alpha1, fbcp, fdp);
    attn_s1<<<512, 256, 214272>>>(x, fbcp, fdp, alpha1, y1p);

    // ---- Stage 2 (z==8 slice of conv_fbc packs Wd2 -> g_wbf) -------------
    conv_fbc_tc<<<dim3(128, 1, 9), 256, FBC_SMEM>>>(
        Wb2, bb2, Wc2, bc2, x, y1p, alpha1, alpha2, Wd2, fbcp);
    attn_zhat<<<2048, 256, ZA_TOT * 4>>>(x, y1p, fbcp, alpha1, alpha2, (__nv_bfloat16*)fdp);
    conv_fe_bf<<<dim3(256, 1, NIMG), 256, FE_SMEM>>>(bd2, (const __nv_bfloat16*)fdp,
                                                     x, y1p, alpha1, alpha2, out);
}